// round 9
// baseline (speedup 1.0000x reference)
#include <cuda_runtime.h>
#include <cuda_bf16.h>
#include <math_constants.h>
#include <cstdint>

#define BB 2
#define SS 2048
#define HH 8
#define DK 512
#define TT 4096
#define NH 16

// ---------------- static device scratch ----------------
__device__ __align__(128) int8_t dx1[TT*512],  dx2[TT*512];
__device__ __align__(128) int8_t dwq1[4096*512], dwq2[4096*512];
__device__ __align__(128) int8_t dwk1[4096*512], dwk2[4096*512];
__device__ __align__(128) int8_t dwv1[4096*512], dwv2[4096*512];
__device__ __align__(128) int8_t dwu1[512*4096], dwu2[512*4096];
__device__ __align__(128) int8_t dho1[(size_t)TT*4096], dho2[(size_t)TT*4096];
__device__ float s_x[TT], s_wq[4096], s_wk[4096], s_wv[4096], s_wu[512], s_ho[TT];

__device__ __nv_bfloat16 g_qh[NH*SS*DK], g_ql[NH*SS*DK];
__device__ __nv_bfloat16 g_kh[NH*SS*DK], g_kl[NH*SS*DK];
__device__ __nv_bfloat16 g_vh[NH*SS*DK], g_vl[NH*SS*DK];     // V natural [bh][t][e]
__device__ float         g_s [(size_t)NH*SS*SS];             // fp32 scores (lower tri)
__device__ __nv_bfloat16 g_ph[(size_t)NH*SS*SS], g_pl[(size_t)NH*SS*SS];
__device__ float         g_ho[(size_t)TT*4096];              // heads_out fp32

// ---------------- common helpers ----------------
__device__ __forceinline__ uint32_t smem_u32(const void* p){
    uint32_t a; asm("{ .reg .u64 t; cvta.to.shared.u64 t, %1; cvt.u32.u64 %0, t; }":"=r"(a):"l"(p)); return a;
}
__device__ __forceinline__ void ldsm4(uint32_t* r, uint32_t addr){
    asm volatile("ldmatrix.sync.aligned.m8n8.x4.shared.b16 {%0,%1,%2,%3}, [%4];"
        : "=r"(r[0]),"=r"(r[1]),"=r"(r[2]),"=r"(r[3]) : "r"(addr));
}
__device__ __forceinline__ void ldsm4t(uint32_t* r, uint32_t addr){
    asm volatile("ldmatrix.sync.aligned.m8n8.x4.trans.shared.b16 {%0,%1,%2,%3}, [%4];"
        : "=r"(r[0]),"=r"(r[1]),"=r"(r[2]),"=r"(r[3]) : "r"(addr));
}
__device__ __forceinline__ void mma16816(float* c, const uint32_t* a, uint32_t b0, uint32_t b1){
    asm volatile("mma.sync.aligned.m16n8k16.row.col.f32.bf16.bf16.f32 "
        "{%0,%1,%2,%3}, {%4,%5,%6,%7}, {%8,%9}, {%0,%1,%2,%3};"
        : "+f"(c[0]),"+f"(c[1]),"+f"(c[2]),"+f"(c[3])
        : "r"(a[0]),"r"(a[1]),"r"(a[2]),"r"(a[3]), "r"(b0),"r"(b1));
}
__device__ __forceinline__ void imma16832(int* c, const uint32_t* a, uint32_t b0, uint32_t b1){
    asm volatile("mma.sync.aligned.m16n8k32.row.col.s32.s8.s8.s32 "
        "{%0,%1,%2,%3}, {%4,%5,%6,%7}, {%8,%9}, {%0,%1,%2,%3};"
        : "+r"(c[0]),"+r"(c[1]),"+r"(c[2]),"+r"(c[3])
        : "r"(a[0]),"r"(a[1]),"r"(a[2]),"r"(a[3]), "r"(b0),"r"(b1));
}
__device__ __forceinline__ void cp16(uint32_t dst, const void* src){
    asm volatile("cp.async.cg.shared.global [%0], [%1], 16;" :: "r"(dst), "l"(src) : "memory");
}
#define CP_COMMIT() asm volatile("cp.async.commit_group;" ::: "memory")
template<int N> __device__ __forceinline__ void cp_wait(){
    asm volatile("cp.async.wait_group %0;" :: "n"(N) : "memory");
}
__device__ __forceinline__ uint32_t swzA(uint32_t row, uint32_t ch){
    return row * 64 + ((ch ^ ((row >> 1) & 3)) << 4);
}
__device__ __forceinline__ uint32_t swzB(uint32_t row, uint32_t ch){
    return row * 256 + ((ch ^ (row & 7)) << 4);
}
__device__ __forceinline__ __nv_bfloat162 split_hi(float a, float b, __nv_bfloat162& lo){
    __nv_bfloat16 h0 = __float2bfloat16(a), h1 = __float2bfloat16(b);
    lo = __nv_bfloat162(__float2bfloat16(a - __bfloat162float(h0)),
                        __float2bfloat16(b - __bfloat162float(h1)));
    return __nv_bfloat162(h0, h1);
}

// ====================== bf16x3 GEMM (proven R6 core) ========================
#define BSTAGE 32768u
#define BNSTAGE 3
#define BSMEM (BSTAGE*BNSTAGE)   // 98304

template<int EPI, bool BT>   // EPI: 0 fp32+mask | 1 fp32 plain
__device__ void gemm_mma(
    const __nv_bfloat16* __restrict__ Ah, const __nv_bfloat16* __restrict__ Al, int lda,
    const __nv_bfloat16* __restrict__ Bh, const __nv_bfloat16* __restrict__ Bl, int ldb,
    int kCount, int m0, int n0, float scale,
    float* __restrict__ Cf, int ldc)
{
    extern __shared__ char sm[];
    const int tid = threadIdx.x, lane = tid & 31, wid = tid >> 5;
    const int wm = wid & 3, wn = wid >> 2;
    const int g = lane >> 2, t4 = lane & 3;
    const uint32_t sbase = smem_u32(sm);

    const int mtx = lane >> 3, ri = lane & 7;
    const int lrow = ((mtx & 1) << 3) + ri;
    const int lkh  = mtx >> 1;
    const int brow = ((lane >> 4) << 3) + ri;
    const int bchh = (lane >> 3) & 1;

    const __nv_bfloat16* Ap[2] = {Ah, Al};
    const __nv_bfloat16* Bp[2] = {Bh, Bl};

    float acc[64];
#pragma unroll
    for (int i = 0; i < 64; i++) acc[i] = 0.f;

    const int nk = kCount >> 5;

    auto load_chunk = [&](int kc){
        const uint32_t sb = sbase + (uint32_t)(kc % BNSTAGE) * BSTAGE;
        const int k0 = kc << 5;
#pragma unroll
        for (int p = 0; p < 2; p++)
#pragma unroll
            for (int i = 0; i < 2; i++) {
                int lin = tid + i * 256;
                int r = lin >> 2, ch = lin & 3;
                cp16(sb + p * 8192 + swzA(r, ch),
                     Ap[p] + (size_t)(m0 + r) * lda + k0 + ch * 8);
            }
        if (BT) {
#pragma unroll
            for (int p = 0; p < 2; p++)
#pragma unroll
                for (int i = 0; i < 2; i++) {
                    int lin = tid + i * 256;
                    int r = lin >> 2, ch = lin & 3;
                    cp16(sb + 16384 + p * 8192 + swzA(r, ch),
                         Bp[p] + (size_t)(n0 + r) * ldb + k0 + ch * 8);
                }
        } else {
#pragma unroll
            for (int p = 0; p < 2; p++)
#pragma unroll
                for (int i = 0; i < 2; i++) {
                    int lin = tid + i * 256;
                    int r = lin >> 4, ch = lin & 15;
                    cp16(sb + 16384 + p * 8192 + swzB(r, ch),
                         Bp[p] + (size_t)(k0 + r) * ldb + n0 + ch * 8);
                }
        }
    };

    load_chunk(0);            CP_COMMIT();
    if (nk > 1) load_chunk(1);
    CP_COMMIT();

    for (int kc = 0; kc < nk; kc++) {
        if (kc + 2 < nk) load_chunk(kc + 2);
        CP_COMMIT();
        cp_wait<2>();
        __syncthreads();

        const uint32_t cb = sbase + (uint32_t)(kc % BNSTAGE) * BSTAGE;
#pragma unroll
        for (int kk = 0; kk < 2; kk++) {
            const int ch = kk * 2 + lkh;
            uint32_t aH[8], aL[8];
#pragma unroll
            for (int s = 0; s < 2; s++) {
                uint32_t off = swzA((uint32_t)(wm * 32 + s * 16 + lrow), ch);
                ldsm4(aH + s * 4, cb + off);
                ldsm4(aL + s * 4, cb + 8192 + off);
            }
#pragma unroll
            for (int nb = 0; nb < 4; nb++) {
                uint32_t bh[4], bl[4];
                if (BT) {
                    uint32_t off = swzA((uint32_t)(wn * 64 + nb * 16 + lrow), ch);
                    ldsm4(bh, cb + 16384 + off);
                    ldsm4(bl, cb + 24576 + off);
                } else {
                    uint32_t off = swzB((uint32_t)(kk * 16 + brow),
                                        (uint32_t)(wn * 8 + nb * 2 + bchh));
                    ldsm4t(bh, cb + 16384 + off);
                    ldsm4t(bl, cb + 24576 + off);
                }
#pragma unroll
                for (int mi = 0; mi < 2; mi++) {
#pragma unroll
                    for (int sub = 0; sub < 2; sub++) {
                        float* c = acc + (mi * 8 + nb * 2 + sub) * 4;
                        mma16816(c, aH + mi * 4, bh[sub], bh[sub + 2]);
                        mma16816(c, aH + mi * 4, bl[sub], bl[sub + 2]);
                        mma16816(c, aL + mi * 4, bh[sub], bh[sub + 2]);
                    }
                }
            }
        }
        __syncthreads();
    }

#pragma unroll
    for (int mi = 0; mi < 2; mi++) {
#pragma unroll
        for (int nbi = 0; nbi < 8; nbi++) {
            const float* c = acc + (mi * 8 + nbi) * 4;
            int rl = wm * 32 + mi * 16 + g;
            int cl = wn * 64 + nbi * 8 + 2 * t4;
            int gr0 = m0 + rl, gc = n0 + cl;
            float v0 = c[0] * scale, v1 = c[1] * scale;
            float v2 = c[2] * scale, v3 = c[3] * scale;
            if (EPI == 0) {
                if (gc     > gr0)     v0 = -CUDART_INF_F;
                if (gc + 1 > gr0)     v1 = -CUDART_INF_F;
                if (gc     > gr0 + 8) v2 = -CUDART_INF_F;
                if (gc + 1 > gr0 + 8) v3 = -CUDART_INF_F;
            }
            *reinterpret_cast<float2*>(Cf + (size_t)gr0 * ldc + gc)       = make_float2(v0, v1);
            *reinterpret_cast<float2*>(Cf + (size_t)(gr0 + 8) * ldc + gc) = make_float2(v2, v3);
        }
    }
}

// ====================== int8 two-digit GEMM =================================
#define ISTAGE 24576u
#define INSTAGE 3
#define ISMEM (ISTAGE*INSTAGE)   // 73728

// NT GEMM 64(M) x 128(N) x BK=64. D = sA[r]*sB[c]*cst*(16384*acc14 + 128*accX).
// EPI: 0 = fp32 store (Cf pre-offset); 1 = split-bf16 into Oh/Ol (pre-offset).
template<int EPI>
__device__ void gemm_i8(
    const int8_t* __restrict__ A1, const int8_t* __restrict__ A2, int lda,
    const int8_t* __restrict__ B1, const int8_t* __restrict__ B2, int ldb,
    int kCount, int m0, int n0, float cst,
    const float* __restrict__ sA, const float* __restrict__ sB,
    float* __restrict__ Cf, int ldc,
    __nv_bfloat16* __restrict__ Oh, __nv_bfloat16* __restrict__ Ol, int orow)
{
    extern __shared__ char sm[];
    const int tid = threadIdx.x, lane = tid & 31, wid = tid >> 5;
    const int wm = wid & 1, wn = wid >> 1;
    const int g = lane >> 2, t4 = lane & 3;
    const uint32_t sbase = smem_u32(sm);

    const int mtx = lane >> 3, ri = lane & 7;
    const int lrow = ((mtx & 1) << 3) + ri;
    const int lkh  = mtx >> 1;

    const int8_t* A1p = A1 + (size_t)m0 * lda;
    const int8_t* A2p = A2 + (size_t)m0 * lda;
    const int8_t* B1p = B1 + (size_t)n0 * ldb;
    const int8_t* B2p = B2 + (size_t)n0 * ldb;

    int acc14[32], accX[32];
#pragma unroll
    for (int i = 0; i < 32; i++) { acc14[i] = 0; accX[i] = 0; }

    const int nk = kCount >> 6;

    auto load_chunk = [&](int kc){
        const uint32_t sb = sbase + (uint32_t)(kc % INSTAGE) * ISTAGE;
        const int k0 = kc << 6;
        {
            int r = tid >> 2, ch = tid & 3;
            uint32_t off = swzA(r, ch);
            cp16(sb + off,        A1p + (size_t)r * lda + k0 + ch * 16);
            cp16(sb + 4096 + off, A2p + (size_t)r * lda + k0 + ch * 16);
        }
#pragma unroll
        for (int i = 0; i < 2; i++) {
            int lin = tid + i * 256;
            int r = lin >> 2, ch = lin & 3;
            uint32_t off = swzA(r, ch);
            cp16(sb + 8192  + off, B1p + (size_t)r * ldb + k0 + ch * 16);
            cp16(sb + 16384 + off, B2p + (size_t)r * ldb + k0 + ch * 16);
        }
    };

    load_chunk(0);            CP_COMMIT();
    if (nk > 1) load_chunk(1);
    CP_COMMIT();

    for (int kc = 0; kc < nk; kc++) {
        if (kc + 2 < nk) load_chunk(kc + 2);
        CP_COMMIT();
        cp_wait<2>();
        __syncthreads();

        const uint32_t cb = sbase + (uint32_t)(kc % INSTAGE) * ISTAGE;
#pragma unroll
        for (int kk = 0; kk < 2; kk++) {
            const uint32_t ch = kk * 2 + lkh;
            uint32_t a1[8], a2[8];
#pragma unroll
            for (int s = 0; s < 2; s++) {
                uint32_t off = swzA((uint32_t)(wm * 32 + s * 16 + lrow), ch);
                ldsm4(a1 + s * 4, cb + off);
                ldsm4(a2 + s * 4, cb + 4096 + off);
            }
#pragma unroll
            for (int nb = 0; nb < 2; nb++) {
                uint32_t b1[4], b2[4];
                uint32_t off = swzA((uint32_t)(wn * 32 + nb * 16 + lrow), ch);
                ldsm4(b1, cb + 8192  + off);
                ldsm4(b2, cb + 16384 + off);
#pragma unroll
                for (int mi = 0; mi < 2; mi++) {
#pragma unroll
                    for (int sub = 0; sub < 2; sub++) {
                        int idx = (mi * 4 + nb * 2 + sub) * 4;
                        imma16832(acc14 + idx, a1 + mi * 4, b1[sub], b1[sub + 2]);
                        imma16832(accX  + idx, a1 + mi * 4, b2[sub], b2[sub + 2]);
                        imma16832(accX  + idx, a2 + mi * 4, b1[sub], b1[sub + 2]);
                    }
                }
            }
        }
        __syncthreads();
    }

#pragma unroll
    for (int mi = 0; mi < 2; mi++) {
        int rl0 = wm * 32 + mi * 16 + g;
        float sa0 = __ldg(sA + rl0) * cst;
        float sa1 = __ldg(sA + rl0 + 8) * cst;
#pragma unroll
        for (int j = 0; j < 4; j++) {
            int idx = (mi * 4 + j) * 4;
            int cl = wn * 32 + j * 8 + 2 * t4;
            float sb0 = __ldg(sB + cl);
            float sb1 = __ldg(sB + cl + 1);
            float f0 = 128.f * fmaf(128.f, (float)acc14[idx + 0], (float)accX[idx + 0]);
            float f1 = 128.f * fmaf(128.f, (float)acc14[idx + 1], (float)accX[idx + 1]);
            float f2 = 128.f * fmaf(128.f, (float)acc14[idx + 2], (float)accX[idx + 2]);
            float f3 = 128.f * fmaf(128.f, (float)acc14[idx + 3], (float)accX[idx + 3]);
            float v0 = f0 * sa0 * sb0, v1 = f1 * sa0 * sb1;
            float v2 = f2 * sa1 * sb0, v3 = f3 * sa1 * sb1;
            if (EPI == 0) {
                *reinterpret_cast<float2*>(Cf + (size_t)rl0 * ldc + cl)       = make_float2(v0, v1);
                *reinterpret_cast<float2*>(Cf + (size_t)(rl0 + 8) * ldc + cl) = make_float2(v2, v3);
            } else {
                __nv_bfloat162 lo01, lo23;
                __nv_bfloat162 hi01 = split_hi(v0, v1, lo01);
                __nv_bfloat162 hi23 = split_hi(v2, v3, lo23);
                size_t o0 = (size_t)(m0 + rl0) * orow + cl;
                size_t o1 = o0 + (size_t)8 * orow;
                *reinterpret_cast<__nv_bfloat162*>(Oh + o0) = hi01;
                *reinterpret_cast<__nv_bfloat162*>(Ol + o0) = lo01;
                *reinterpret_cast<__nv_bfloat162*>(Oh + o1) = hi23;
                *reinterpret_cast<__nv_bfloat162*>(Ol + o1) = lo23;
            }
        }
    }
}

// ---------------------------------------------------------------------------
// Row quantize. FIXED: digits must be SIGNED bytes — plain (char) is UNSIGNED
// on the aarch64 build host, and device float->u8 cvt saturates negatives to 0.
__device__ __forceinline__ void q2dig(float t, int8_t& d1, int8_t& d2){
    int hi = __float2int_rn(t * 0.0078125f);
    d1 = (int8_t)hi;
    d2 = (int8_t)__float2int_rn(fmaf(-128.f, (float)hi, t));
}
__global__ void __launch_bounds__(256) k_rowquant(
    const float* __restrict__ src, int8_t* __restrict__ d1,
    int8_t* __restrict__ d2, float* __restrict__ sc, int C)
{
    int row  = blockIdx.x * 8 + (threadIdx.x >> 5);
    int lane = threadIdx.x & 31;
    const float4* p = reinterpret_cast<const float4*>(src + (size_t)row * C);
    int n4 = C >> 2;

    float mx = 0.f;
    for (int i = lane; i < n4; i += 32) {
        float4 v = p[i];
        mx = fmaxf(mx, fmaxf(fmaxf(fabsf(v.x), fabsf(v.y)), fmaxf(fabsf(v.z), fabsf(v.w))));
    }
#pragma unroll
    for (int o = 16; o; o >>= 1) mx = fmaxf(mx, __shfl_xor_sync(0xffffffffu, mx, o));
    float inv = (mx > 0.f) ? 16256.f / mx : 0.f;
    if (lane == 0) sc[row] = mx * (1.f / 16256.f);

    char4* q1 = reinterpret_cast<char4*>(d1 + (size_t)row * C);
    char4* q2 = reinterpret_cast<char4*>(d2 + (size_t)row * C);
    for (int i = lane; i < n4; i += 32) {
        float4 v = p[i];
        int8_t a1, a2, b1, b2, c1v, c2v, e1, e2;
        q2dig(v.x * inv, a1, a2);
        q2dig(v.y * inv, b1, b2);
        q2dig(v.z * inv, c1v, c2v);
        q2dig(v.w * inv, e1, e2);
        char4 o1, o2;
        o1.x = a1; o1.y = b1; o1.z = c1v; o1.w = e1;
        o2.x = a2; o2.y = b2; o2.z = c2v; o2.w = e2;
        q1[i] = o1; q2[i] = o2;
    }
}

// QKV projections via int8; epilogue emits split-bf16 q/k/v.
__global__ void __launch_bounds__(256, 2) k_qkv_i8(void)
{
    int n0 = blockIdx.x * 128, m0 = blockIdx.y * 64, z = blockIdx.z;
    int b = m0 >> 11, h = n0 >> 9, e0 = n0 & 511;
    const int8_t *W1, *W2;
    const float* sw;
    __nv_bfloat16 *OH, *OL;
    if (z == 0)      { W1 = dwq1; W2 = dwq2; sw = s_wq; OH = g_qh; OL = g_ql; }
    else if (z == 1) { W1 = dwk1; W2 = dwk2; sw = s_wk; OH = g_kh; OL = g_kl; }
    else             { W1 = dwv1; W2 = dwv2; sw = s_wv; OH = g_vh; OL = g_vl; }
    size_t base = ((size_t)(b * 8 + h) * SS) * 512 + e0 - (size_t)b * SS * 512;
    gemm_i8<1>(dx1, dx2, 512, W1, W2, 512, 512, m0, n0, 1.f,
               s_x + m0, sw + n0, nullptr, 0, OH + base, OL + base, 512);
}

__global__ void __launch_bounds__(256, 2) k_scores_mma(void)
{
    int bh = blockIdx.z, n0 = blockIdx.x * 128, m0 = blockIdx.y * 128;
    if (n0 > m0) return;
    float* Cf = g_s + (size_t)bh * SS * SS;
    size_t ob = (size_t)bh * SS * DK;
    gemm_mma<0, true>(g_qh + ob, g_ql + ob, 512, g_kh + ob, g_kl + ob, 512,
                      512, m0, n0, 0.04419417382415922f, Cf, SS);
}

__global__ void __launch_bounds__(256) k_softmax(void)
{
    int row  = blockIdx.x * 8 + (threadIdx.x >> 5);
    int lane = threadIdx.x & 31;
    int r    = row & (SS - 1);
    int rt   = r >> 7;
    const float4* p = reinterpret_cast<const float4*>(g_s + (size_t)row * SS);
    uint2* ph = reinterpret_cast<uint2*>(g_ph + (size_t)row * SS);
    uint2* pl = reinterpret_cast<uint2*>(g_pl + (size_t)row * SS);

    float4 v[16];
    float mx = -CUDART_INF_F;
#pragma unroll
    for (int i = 0; i < 16; i++) {
        if (i <= rt) {
            v[i] = p[lane + i * 32];
            mx = fmaxf(mx, fmaxf(fmaxf(v[i].x, v[i].y), fmaxf(v[i].z, v[i].w)));
        }
    }
#pragma unroll
    for (int o = 16; o; o >>= 1) mx = fmaxf(mx, __shfl_xor_sync(0xffffffffu, mx, o));
    float sum = 0.f;
#pragma unroll
    for (int i = 0; i < 16; i++) {
        if (i > rt) continue;
        v[i].x = __expf(v[i].x - mx); v[i].y = __expf(v[i].y - mx);
        v[i].z = __expf(v[i].z - mx); v[i].w = __expf(v[i].w - mx);
        sum += (v[i].x + v[i].y) + (v[i].z + v[i].w);
    }
#pragma unroll
    for (int o = 16; o; o >>= 1) sum += __shfl_xor_sync(0xffffffffu, sum, o);
    float inv = 1.f / sum;
#pragma unroll
    for (int i = 0; i < 16; i++) {
        if (i > rt) continue;
        float a0 = v[i].x*inv, a1 = v[i].y*inv, a2 = v[i].z*inv, a3 = v[i].w*inv;
        __nv_bfloat162 lo01, lo23;
        __nv_bfloat162 hi01 = split_hi(a0, a1, lo01);
        __nv_bfloat162 hi23 = split_hi(a2, a3, lo23);
        ph[lane + i*32] = make_uint2(*reinterpret_cast<uint32_t*>(&hi01),
                                     *reinterpret_cast<uint32_t*>(&hi23));
        pl[lane + i*32] = make_uint2(*reinterpret_cast<uint32_t*>(&lo01),
                                     *reinterpret_cast<uint32_t*>(&lo23));
    }
}

// PV: NN gemm, fp32 out into g_ho [t][4096]
__global__ void __launch_bounds__(256, 2) k_pv_mma(void)
{
    int bh = blockIdx.z, b = bh >> 3, h = bh & 7;
    int m0 = blockIdx.y * 128, n0 = blockIdx.x * 128;
    const __nv_bfloat16* Ah = g_ph + (size_t)bh * SS * SS;
    const __nv_bfloat16* Al = g_pl + (size_t)bh * SS * SS;
    const __nv_bfloat16* Bh = g_vh + (size_t)bh * SS * DK;
    const __nv_bfloat16* Bl = g_vl + (size_t)bh * SS * DK;
    float* Cf = g_ho + (size_t)b * SS * 4096 + h * 512;
    gemm_mma<1, false>(Ah, Al, SS, Bh, Bl, 512, m0 + 128, m0, n0, 1.f, Cf, 4096);
}

__global__ void __launch_bounds__(256, 2) k_out_i8(float* __restrict__ out)
{
    int m0 = blockIdx.y * 64, n0 = blockIdx.x * 128;
    gemm_i8<0>(dho1, dho2, 4096, dwu1, dwu2, 4096, 4096, m0, n0, 1.f,
               s_ho + m0, s_wu + n0, out + (size_t)m0 * 512 + n0, 512,
               nullptr, nullptr, 0);
}

// ---------------------------------------------------------------------------
extern "C" void kernel_launch(void* const* d_in, const int* in_sizes, int n_in,
                              void* d_out, int out_size)
{
    const float* x  = (const float*)d_in[0];
    const float* Wq = (const float*)d_in[1];
    const float* Wk = (const float*)d_in[2];
    const float* Wv = (const float*)d_in[3];
    const float* Wu = (const float*)d_in[4];
    float* out = (float*)d_out;

    cudaFuncSetAttribute(k_qkv_i8,     cudaFuncAttributeMaxDynamicSharedMemorySize, ISMEM);
    cudaFuncSetAttribute(k_out_i8,     cudaFuncAttributeMaxDynamicSharedMemorySize, ISMEM);
    cudaFuncSetAttribute(k_scores_mma, cudaFuncAttributeMaxDynamicSharedMemorySize, BSMEM);
    cudaFuncSetAttribute(k_pv_mma,     cudaFuncAttributeMaxDynamicSharedMemorySize, BSMEM);

    int8_t *px1, *px2, *pq1, *pq2, *pk1, *pk2, *pv1, *pv2, *pu1, *pu2, *ph1, *ph2;
    float *psx, *pswq, *pswk, *pswv, *pswu, *psho, *fho;
    cudaGetSymbolAddress((void**)&px1, dx1);  cudaGetSymbolAddress((void**)&px2, dx2);
    cudaGetSymbolAddress((void**)&pq1, dwq1); cudaGetSymbolAddress((void**)&pq2, dwq2);
    cudaGetSymbolAddress((void**)&pk1, dwk1); cudaGetSymbolAddress((void**)&pk2, dwk2);
    cudaGetSymbolAddress((void**)&pv1, dwv1); cudaGetSymbolAddress((void**)&pv2, dwv2);
    cudaGetSymbolAddress((void**)&pu1, dwu1); cudaGetSymbolAddress((void**)&pu2, dwu2);
    cudaGetSymbolAddress((void**)&ph1, dho1); cudaGetSymbolAddress((void**)&ph2, dho2);
    cudaGetSymbolAddress((void**)&psx, s_x);  cudaGetSymbolAddress((void**)&pswq, s_wq);
    cudaGetSymbolAddress((void**)&pswk, s_wk); cudaGetSymbolAddress((void**)&pswv, s_wv);
    cudaGetSymbolAddress((void**)&pswu, s_wu); cudaGetSymbolAddress((void**)&psho, s_ho);
    cudaGetSymbolAddress((void**)&fho, g_ho);

    k_rowquant<<<TT/8,   256>>>(x,  px1, px2, psx,  512);
    k_rowquant<<<4096/8, 256>>>(Wq, pq1, pq2, pswq, 512);
    k_rowquant<<<4096/8, 256>>>(Wk, pk1, pk2, pswk, 512);
    k_rowquant<<<4096/8, 256>>>(Wv, pv1, pv2, pswv, 512);
    k_rowquant<<<512/8,  256>>>(Wu, pu1, pu2, pswu, 4096);

    k_qkv_i8    <<<dim3(32, 64, 3),  256, ISMEM>>>();
    k_scores_mma<<<dim3(16, 16, NH), 256, BSMEM>>>();
    k_softmax   <<<NH * SS / 8, 256>>>();
    k_pv_mma    <<<dim3(4, 16, NH),  256, BSMEM>>>();

    k_rowquant<<<TT/8, 256>>>(fho, ph1, ph2, psho, 4096);
    k_out_i8<<<dim3(4, 64, 1), 256, ISMEM>>>(out);
}

// round 10
// speedup vs baseline: 1.6559x; 1.6559x over previous
#include <cuda_runtime.h>
#include <cuda_bf16.h>
#include <math_constants.h>
#include <cstdint>

#define BB 2
#define SS 2048
#define HH 8
#define DK 512
#define TT (BB*SS)      // 4096 tokens
#define NH (BB*HH)      // 16 (b,h) pairs

// ---------------- static device scratch (no allocs allowed) ----------------
__device__ __nv_bfloat16 g_xh[TT*DK],  g_xl[TT*DK];
__device__ __nv_bfloat16 g_wqh[4096*512], g_wql[4096*512];
__device__ __nv_bfloat16 g_wkh[4096*512], g_wkl[4096*512];
__device__ __nv_bfloat16 g_wvh[4096*512], g_wvl[4096*512];
__device__ __nv_bfloat16 g_wuh[512*4096], g_wul[512*4096];
__device__ __nv_bfloat16 g_qh[NH*SS*DK], g_ql[NH*SS*DK];
__device__ __nv_bfloat16 g_kh[NH*SS*DK], g_kl[NH*SS*DK];
__device__ __nv_bfloat16 g_vh[NH*SS*DK], g_vl[NH*SS*DK];     // V natural [bh][t][e]
__device__ float         g_s [(size_t)NH*SS*SS];             // fp32 scores (lower tri)
__device__ __nv_bfloat16 g_ph[(size_t)NH*SS*SS], g_pl[(size_t)NH*SS*SS];
__device__ __nv_bfloat16 g_hoh[(size_t)TT*4096], g_hol[(size_t)TT*4096];

// ---------------- helpers ----------------
__device__ __forceinline__ uint32_t smem_u32(const void* p){
    uint32_t a; asm("{ .reg .u64 t; cvta.to.shared.u64 t, %1; cvt.u32.u64 %0, t; }":"=r"(a):"l"(p)); return a;
}
__device__ __forceinline__ void ldsm4(uint32_t* r, uint32_t addr){
    asm volatile("ldmatrix.sync.aligned.m8n8.x4.shared.b16 {%0,%1,%2,%3}, [%4];"
        : "=r"(r[0]),"=r"(r[1]),"=r"(r[2]),"=r"(r[3]) : "r"(addr));
}
__device__ __forceinline__ void ldsm4t(uint32_t* r, uint32_t addr){
    asm volatile("ldmatrix.sync.aligned.m8n8.x4.trans.shared.b16 {%0,%1,%2,%3}, [%4];"
        : "=r"(r[0]),"=r"(r[1]),"=r"(r[2]),"=r"(r[3]) : "r"(addr));
}
__device__ __forceinline__ void mma16816(float* c, const uint32_t* a, uint32_t b0, uint32_t b1){
    asm volatile("mma.sync.aligned.m16n8k16.row.col.f32.bf16.bf16.f32 "
        "{%0,%1,%2,%3}, {%4,%5,%6,%7}, {%8,%9}, {%0,%1,%2,%3};"
        : "+f"(c[0]),"+f"(c[1]),"+f"(c[2]),"+f"(c[3])
        : "r"(a[0]),"r"(a[1]),"r"(a[2]),"r"(a[3]), "r"(b0),"r"(b1));
}
__device__ __forceinline__ void cp16(uint32_t dst, const void* src){
    asm volatile("cp.async.cg.shared.global [%0], [%1], 16;" :: "r"(dst), "l"(src) : "memory");
}
#define CP_COMMIT() asm volatile("cp.async.commit_group;" ::: "memory")
template<int N> __device__ __forceinline__ void cp_wait(){
    asm volatile("cp.async.wait_group %0;" :: "n"(N) : "memory");
}
__device__ __forceinline__ uint32_t swzA(uint32_t row, uint32_t ch){
    return row * 64 + ((ch ^ ((row >> 1) & 3)) << 4);
}
__device__ __forceinline__ uint32_t swzB(uint32_t row, uint32_t ch){
    return row * 256 + ((ch ^ (row & 7)) << 4);
}

#define STAGE 32768u        // 4 parts x 8KB per stage (BK=32)
#define NSTAGE 3
#define SMEM_DYN (STAGE*NSTAGE)   // 98304 -> 2 CTAs/SM

// ---------------------------------------------------------------------------
// bf16x3 warp-MMA GEMM, 3-stage cp.async, BK=32, TERM-MAJOR issue order:
// per nb-pair, all 8 accumulators get term hh, then hl, then lh -> dependent
// HMMA writes to the same accumulator are 8 instructions apart.
// ---------------------------------------------------------------------------
template<int EPI, bool BT>
__device__ void gemm_mma(
    const __nv_bfloat16* __restrict__ Ah, const __nv_bfloat16* __restrict__ Al, int lda,
    const __nv_bfloat16* __restrict__ Bh, const __nv_bfloat16* __restrict__ Bl, int ldb,
    int kCount, int m0, int n0, float scale,
    float* __restrict__ Cf, int ldc,
    __nv_bfloat16* __restrict__ Oh, __nv_bfloat16* __restrict__ Ol, int orow)
{
    extern __shared__ char sm[];
    const int tid = threadIdx.x, lane = tid & 31, wid = tid >> 5;
    const int wm = wid & 3, wn = wid >> 2;
    const int g = lane >> 2, t4 = lane & 3;
    const uint32_t sbase = smem_u32(sm);

    const int mtx = lane >> 3, ri = lane & 7;
    const int lrow = ((mtx & 1) << 3) + ri;
    const int lkh  = mtx >> 1;
    const int brow = ((lane >> 4) << 3) + ri;
    const int bchh = (lane >> 3) & 1;

    const __nv_bfloat16* Ap[2] = {Ah, Al};
    const __nv_bfloat16* Bp[2] = {Bh, Bl};

    float acc[64];
#pragma unroll
    for (int i = 0; i < 64; i++) acc[i] = 0.f;

    const int nk = kCount >> 5;

    auto load_chunk = [&](int kc){
        const uint32_t sb = sbase + (uint32_t)(kc % NSTAGE) * STAGE;
        const int k0 = kc << 5;
#pragma unroll
        for (int p = 0; p < 2; p++)
#pragma unroll
            for (int i = 0; i < 2; i++) {
                int lin = tid + i * 256;
                int r = lin >> 2, ch = lin & 3;
                cp16(sb + p * 8192 + swzA(r, ch),
                     Ap[p] + (size_t)(m0 + r) * lda + k0 + ch * 8);
            }
        if (BT) {
#pragma unroll
            for (int p = 0; p < 2; p++)
#pragma unroll
                for (int i = 0; i < 2; i++) {
                    int lin = tid + i * 256;
                    int r = lin >> 2, ch = lin & 3;
                    cp16(sb + 16384 + p * 8192 + swzA(r, ch),
                         Bp[p] + (size_t)(n0 + r) * ldb + k0 + ch * 8);
                }
        } else {
#pragma unroll
            for (int p = 0; p < 2; p++)
#pragma unroll
                for (int i = 0; i < 2; i++) {
                    int lin = tid + i * 256;
                    int r = lin >> 4, ch = lin & 15;
                    cp16(sb + 16384 + p * 8192 + swzB(r, ch),
                         Bp[p] + (size_t)(k0 + r) * ldb + n0 + ch * 8);
                }
        }
    };

    load_chunk(0);            CP_COMMIT();
    if (nk > 1) load_chunk(1);
    CP_COMMIT();

    for (int kc = 0; kc < nk; kc++) {
        if (kc + 2 < nk) load_chunk(kc + 2);
        CP_COMMIT();
        cp_wait<2>();
        __syncthreads();

        const uint32_t cb = sbase + (uint32_t)(kc % NSTAGE) * STAGE;
#pragma unroll
        for (int kk = 0; kk < 2; kk++) {
            const int ch = kk * 2 + lkh;
            uint32_t aH[8], aL[8];
#pragma unroll
            for (int s = 0; s < 2; s++) {
                uint32_t off = swzA((uint32_t)(wm * 32 + s * 16 + lrow), ch);
                ldsm4(aH + s * 4, cb + off);
                ldsm4(aL + s * 4, cb + 8192 + off);
            }
#pragma unroll
            for (int nbp = 0; nbp < 2; nbp++) {
                uint32_t bh[8], bl[8];
#pragma unroll
                for (int q = 0; q < 2; q++) {
                    int nb = nbp * 2 + q;
                    if (BT) {
                        uint32_t off = swzA((uint32_t)(wn * 64 + nb * 16 + lrow), ch);
                        ldsm4(bh + q * 4, cb + 16384 + off);
                        ldsm4(bl + q * 4, cb + 24576 + off);
                    } else {
                        uint32_t off = swzB((uint32_t)(kk * 16 + brow),
                                            (uint32_t)(wn * 8 + nb * 2 + bchh));
                        ldsm4t(bh + q * 4, cb + 16384 + off);
                        ldsm4t(bl + q * 4, cb + 24576 + off);
                    }
                }
                // term-major: 8 independent accumulators between dependent writes
#pragma unroll
                for (int t = 0; t < 3; t++) {
#pragma unroll
                    for (int q = 0; q < 2; q++) {
#pragma unroll
                        for (int mi = 0; mi < 2; mi++) {
#pragma unroll
                            for (int sub = 0; sub < 2; sub++) {
                                int nb = nbp * 2 + q;
                                float* c = acc + (mi * 8 + nb * 2 + sub) * 4;
                                const uint32_t* a = (t == 2) ? (aL + mi * 4) : (aH + mi * 4);
                                const uint32_t* b = (t == 1) ? (bl + q * 4) : (bh + q * 4);
                                mma16816(c, a, b[sub], b[sub + 2]);
                            }
                        }
                    }
                }
            }
        }
        __syncthreads();
    }

    // ---- epilogue straight from registers
#pragma unroll
    for (int mi = 0; mi < 2; mi++) {
#pragma unroll
        for (int nbi = 0; nbi < 8; nbi++) {
            const float* c = acc + (mi * 8 + nbi) * 4;
            int rl = wm * 32 + mi * 16 + g;
            int cl = wn * 64 + nbi * 8 + 2 * t4;
            if (EPI <= 1) {
                int gr0 = m0 + rl, gc = n0 + cl;
                float v0 = c[0] * scale, v1 = c[1] * scale;
                float v2 = c[2] * scale, v3 = c[3] * scale;
                if (EPI == 0) {
                    if (gc     > gr0)     v0 = -CUDART_INF_F;
                    if (gc + 1 > gr0)     v1 = -CUDART_INF_F;
                    if (gc     > gr0 + 8) v2 = -CUDART_INF_F;
                    if (gc + 1 > gr0 + 8) v3 = -CUDART_INF_F;
                }
                *reinterpret_cast<float2*>(Cf + (size_t)gr0 * ldc + gc)       = make_float2(v0, v1);
                *reinterpret_cast<float2*>(Cf + (size_t)(gr0 + 8) * ldc + gc) = make_float2(v2, v3);
            } else {
                __nv_bfloat16 h0 = __float2bfloat16(c[0]);
                __nv_bfloat16 h1 = __float2bfloat16(c[1]);
                __nv_bfloat16 h2 = __float2bfloat16(c[2]);
                __nv_bfloat16 h3 = __float2bfloat16(c[3]);
                __nv_bfloat16 l0 = __float2bfloat16(c[0] - __bfloat162float(h0));
                __nv_bfloat16 l1 = __float2bfloat16(c[1] - __bfloat162float(h1));
                __nv_bfloat16 l2 = __float2bfloat16(c[2] - __bfloat162float(h2));
                __nv_bfloat16 l3 = __float2bfloat16(c[3] - __bfloat162float(h3));
                size_t gm = (size_t)(m0 + rl);
                size_t o0 = gm * orow + cl, o1 = o0 + (size_t)8 * orow;
                *reinterpret_cast<__nv_bfloat162*>(Oh + o0) = __nv_bfloat162(h0, h1);
                *reinterpret_cast<__nv_bfloat162*>(Ol + o0) = __nv_bfloat162(l0, l1);
                *reinterpret_cast<__nv_bfloat162*>(Oh + o1) = __nv_bfloat162(h2, h3);
                *reinterpret_cast<__nv_bfloat162*>(Ol + o1) = __nv_bfloat162(l2, l3);
            }
        }
    }
}

// ---------------------------------------------------------------------------
__global__ void __launch_bounds__(256) k_split_all(
    const float* __restrict__ x,  const float* __restrict__ Wq,
    const float* __restrict__ Wk, const float* __restrict__ Wv,
    const float* __restrict__ Wu)
{
    const int z = blockIdx.y;
    const float* s;
    __nv_bfloat16 *h, *l;
    switch (z) {
        case 0: s = x;  h = g_xh;  l = g_xl;  break;
        case 1: s = Wq; h = g_wqh; l = g_wql; break;
        case 2: s = Wk; h = g_wkh; l = g_wkl; break;
        case 3: s = Wv; h = g_wvh; l = g_wvl; break;
        default: s = Wu; h = g_wuh; l = g_wul; break;
    }
    int i = blockIdx.x * blockDim.x + threadIdx.x;
    float4 v = reinterpret_cast<const float4*>(s)[i];
    __nv_bfloat16 h0=__float2bfloat16(v.x), h1=__float2bfloat16(v.y),
                  h2=__float2bfloat16(v.z), h3=__float2bfloat16(v.w);
    __nv_bfloat16 l0=__float2bfloat16(v.x-__bfloat162float(h0)),
                  l1=__float2bfloat16(v.y-__bfloat162float(h1)),
                  l2=__float2bfloat16(v.z-__bfloat162float(h2)),
                  l3=__float2bfloat16(v.w-__bfloat162float(h3));
    uint2 hv = make_uint2((uint32_t)__bfloat16_as_ushort(h0)|((uint32_t)__bfloat16_as_ushort(h1)<<16),
                          (uint32_t)__bfloat16_as_ushort(h2)|((uint32_t)__bfloat16_as_ushort(h3)<<16));
    uint2 lv = make_uint2((uint32_t)__bfloat16_as_ushort(l0)|((uint32_t)__bfloat16_as_ushort(l1)<<16),
                          (uint32_t)__bfloat16_as_ushort(l2)|((uint32_t)__bfloat16_as_ushort(l3)<<16));
    reinterpret_cast<uint2*>(h)[i] = hv;
    reinterpret_cast<uint2*>(l)[i] = lv;
}

__global__ void __launch_bounds__(256, 2) k_qkv_mma(void)
{
    int n0 = blockIdx.x * 128, m0 = blockIdx.y * 128, z = blockIdx.z;
    int b = m0 >> 11, h = n0 >> 9, e0 = n0 & 511;
    const __nv_bfloat16 *Wh, *Wl;
    __nv_bfloat16 *OH, *OL;
    if (z == 0)      { Wh = g_wqh; Wl = g_wql; OH = g_qh; OL = g_ql; }
    else if (z == 1) { Wh = g_wkh; Wl = g_wkl; OH = g_kh; OL = g_kl; }
    else             { Wh = g_wvh; Wl = g_wvl; OH = g_vh; OL = g_vl; }
    size_t base = ((size_t)(b * HH + h) * SS) * DK + e0 - (size_t)(b * SS) * DK;
    gemm_mma<2, true>(g_xh, g_xl, 512, Wh, Wl, 512, 512, m0, n0, 1.f,
                      nullptr, 0, OH + base, OL + base, 512);
}

__global__ void __launch_bounds__(256, 2) k_scores_mma(void)
{
    int bh = blockIdx.z, n0 = blockIdx.x * 128, m0 = blockIdx.y * 128;
    if (n0 > m0) return;
    float* Cf = g_s + (size_t)bh * SS * SS;
    size_t ob = (size_t)bh * SS * DK;
    gemm_mma<0, true>(g_qh + ob, g_ql + ob, 512, g_kh + ob, g_kl + ob, 512,
                      512, m0, n0, 0.04419417382415922f, Cf, SS, nullptr, nullptr, 0);
}

__global__ void __launch_bounds__(256) k_softmax(void)
{
    int row  = blockIdx.x * 8 + (threadIdx.x >> 5);
    int lane = threadIdx.x & 31;
    int r    = row & (SS - 1);
    int rt   = r >> 7;
    const float4* p = reinterpret_cast<const float4*>(g_s + (size_t)row * SS);
    uint2* ph = reinterpret_cast<uint2*>(g_ph + (size_t)row * SS);
    uint2* pl = reinterpret_cast<uint2*>(g_pl + (size_t)row * SS);

    float4 v[16];
    float mx = -CUDART_INF_F;
#pragma unroll
    for (int i = 0; i < 16; i++) {
        if (i <= rt) {
            v[i] = p[lane + i * 32];
            mx = fmaxf(mx, fmaxf(fmaxf(v[i].x, v[i].y), fmaxf(v[i].z, v[i].w)));
        }
    }
#pragma unroll
    for (int o = 16; o; o >>= 1) mx = fmaxf(mx, __shfl_xor_sync(0xffffffffu, mx, o));
    float sum = 0.0f;
#pragma unroll
    for (int i = 0; i < 16; i++) {
        if (i > rt) continue;
        v[i].x = __expf(v[i].x - mx); v[i].y = __expf(v[i].y - mx);
        v[i].z = __expf(v[i].z - mx); v[i].w = __expf(v[i].w - mx);
        sum += (v[i].x + v[i].y) + (v[i].z + v[i].w);
    }
#pragma unroll
    for (int o = 16; o; o >>= 1) sum += __shfl_xor_sync(0xffffffffu, sum, o);
    float inv = 1.0f / sum;
#pragma unroll
    for (int i = 0; i < 16; i++) {
        if (i > rt) continue;
        float a0 = v[i].x*inv, a1 = v[i].y*inv, a2 = v[i].z*inv, a3 = v[i].w*inv;
        __nv_bfloat16 h0=__float2bfloat16(a0), h1=__float2bfloat16(a1),
                      h2=__float2bfloat16(a2), h3=__float2bfloat16(a3);
        __nv_bfloat16 l0=__float2bfloat16(a0-__bfloat162float(h0)),
                      l1=__float2bfloat16(a1-__bfloat162float(h1)),
                      l2=__float2bfloat16(a2-__bfloat162float(h2)),
                      l3=__float2bfloat16(a3-__bfloat162float(h3));
        ph[lane + i*32] = make_uint2(
            (uint32_t)__bfloat16_as_ushort(h0)|((uint32_t)__bfloat16_as_ushort(h1)<<16),
            (uint32_t)__bfloat16_as_ushort(h2)|((uint32_t)__bfloat16_as_ushort(h3)<<16));
        pl[lane + i*32] = make_uint2(
            (uint32_t)__bfloat16_as_ushort(l0)|((uint32_t)__bfloat16_as_ushort(l1)<<16),
            (uint32_t)__bfloat16_as_ushort(l2)|((uint32_t)__bfloat16_as_ushort(l3)<<16));
    }
}

__global__ void __launch_bounds__(256, 2) k_pv_mma(void)
{
    int bh = blockIdx.z, b = bh >> 3, h = bh & 7;
    int m0 = blockIdx.y * 128, n0 = blockIdx.x * 128;
    const __nv_bfloat16* Ah = g_ph + (size_t)bh * SS * SS;
    const __nv_bfloat16* Al = g_pl + (size_t)bh * SS * SS;
    const __nv_bfloat16* Bh = g_vh + (size_t)bh * SS * DK;
    const __nv_bfloat16* Bl = g_vl + (size_t)bh * SS * DK;
    size_t base = (size_t)b * SS * 4096 + h * 512 + n0;
    gemm_mma<2, false>(Ah, Al, SS, Bh, Bl, 512, m0 + 128, m0, n0, 1.f,
                       nullptr, 0, g_hoh + base, g_hol + base, 4096);
}

__global__ void __launch_bounds__(256, 2) k_out_mma(float* __restrict__ out)
{
    int m0 = blockIdx.y * 128, n0 = blockIdx.x * 128;
    gemm_mma<1, true>(g_hoh, g_hol, 4096, g_wuh, g_wul, 4096, 4096, m0, n0, 1.f,
                      out, 512, nullptr, nullptr, 0);
}

// ---------------------------------------------------------------------------
extern "C" void kernel_launch(void* const* d_in, const int* in_sizes, int n_in,
                              void* d_out, int out_size)
{
    const float* x  = (const float*)d_in[0];
    const float* Wq = (const float*)d_in[1];
    const float* Wk = (const float*)d_in[2];
    const float* Wv = (const float*)d_in[3];
    const float* Wu = (const float*)d_in[4];
    float* out = (float*)d_out;

    cudaFuncSetAttribute(k_qkv_mma,    cudaFuncAttributeMaxDynamicSharedMemorySize, SMEM_DYN);
    cudaFuncSetAttribute(k_scores_mma, cudaFuncAttributeMaxDynamicSharedMemorySize, SMEM_DYN);
    cudaFuncSetAttribute(k_pv_mma,     cudaFuncAttributeMaxDynamicSharedMemorySize, SMEM_DYN);
    cudaFuncSetAttribute(k_out_mma,    cudaFuncAttributeMaxDynamicSharedMemorySize, SMEM_DYN);

    const int n4 = TT * DK / 4;
    k_split_all <<<dim3(n4 / 256, 5), 256>>>(x, Wq, Wk, Wv, Wu);

    k_qkv_mma   <<<dim3(32, 32, 3),  256, SMEM_DYN>>>();
    k_scores_mma<<<dim3(16, 16, NH), 256, SMEM_DYN>>>();
    k_softmax   <<<NH * SS / 8, 256>>>();
    k_pv_mma    <<<dim3(4, 16, NH),  256, SMEM_DYN>>>();
    k_out_mma   <<<dim3(4, 32, 1),   256, SMEM_DYN>>>(out);
}

// round 11
// speedup vs baseline: 1.6741x; 1.0110x over previous
#include <cuda_runtime.h>
#include <cuda_bf16.h>
#include <math_constants.h>
#include <cstdint>

#define BB 2
#define SS 2048
#define HH 8
#define DK 512
#define TT (BB*SS)      // 4096 tokens
#define NH (BB*HH)      // 16 (b,h) pairs

// ---------------- static device scratch (no allocs allowed) ----------------
__device__ __nv_bfloat16 g_xh[TT*DK],  g_xl[TT*DK];
__device__ __nv_bfloat16 g_wqh[4096*512], g_wql[4096*512];
__device__ __nv_bfloat16 g_wkh[4096*512], g_wkl[4096*512];
__device__ __nv_bfloat16 g_wvh[4096*512], g_wvl[4096*512];
__device__ __nv_bfloat16 g_wuh[512*4096], g_wul[512*4096];
__device__ __nv_bfloat16 g_qh[NH*SS*DK], g_ql[NH*SS*DK];
__device__ __nv_bfloat16 g_kh[NH*SS*DK], g_kl[NH*SS*DK];
__device__ __nv_bfloat16 g_vh[NH*SS*DK], g_vl[NH*SS*DK];     // V natural [bh][t][e]
__device__ float         g_s [(size_t)NH*SS*SS];             // fp32 scores (lower tri)
__device__ __nv_bfloat16 g_ph[(size_t)NH*SS*SS], g_pl[(size_t)NH*SS*SS];
__device__ __nv_bfloat16 g_hoh[(size_t)TT*4096], g_hol[(size_t)TT*4096];
__device__ float         g_op[4][(size_t)TT*512];            // out k-split partials

// ---------------- helpers ----------------
__device__ __forceinline__ uint32_t smem_u32(const void* p){
    uint32_t a; asm("{ .reg .u64 t; cvta.to.shared.u64 t, %1; cvt.u32.u64 %0, t; }":"=r"(a):"l"(p)); return a;
}
__device__ __forceinline__ void ldsm4(uint32_t* r, uint32_t addr){
    asm volatile("ldmatrix.sync.aligned.m8n8.x4.shared.b16 {%0,%1,%2,%3}, [%4];"
        : "=r"(r[0]),"=r"(r[1]),"=r"(r[2]),"=r"(r[3]) : "r"(addr));
}
__device__ __forceinline__ void ldsm4t(uint32_t* r, uint32_t addr){
    asm volatile("ldmatrix.sync.aligned.m8n8.x4.trans.shared.b16 {%0,%1,%2,%3}, [%4];"
        : "=r"(r[0]),"=r"(r[1]),"=r"(r[2]),"=r"(r[3]) : "r"(addr));
}
__device__ __forceinline__ void mma16816(float* c, const uint32_t* a, uint32_t b0, uint32_t b1){
    asm volatile("mma.sync.aligned.m16n8k16.row.col.f32.bf16.bf16.f32 "
        "{%0,%1,%2,%3}, {%4,%5,%6,%7}, {%8,%9}, {%0,%1,%2,%3};"
        : "+f"(c[0]),"+f"(c[1]),"+f"(c[2]),"+f"(c[3])
        : "r"(a[0]),"r"(a[1]),"r"(a[2]),"r"(a[3]), "r"(b0),"r"(b1));
}
__device__ __forceinline__ void cp16(uint32_t dst, const void* src){
    asm volatile("cp.async.cg.shared.global [%0], [%1], 16;" :: "r"(dst), "l"(src) : "memory");
}
#define CP_COMMIT() asm volatile("cp.async.commit_group;" ::: "memory")
template<int N> __device__ __forceinline__ void cp_wait(){
    asm volatile("cp.async.wait_group %0;" :: "n"(N) : "memory");
}
__device__ __forceinline__ uint32_t swzA(uint32_t row, uint32_t ch){
    return row * 64 + ((ch ^ ((row >> 1) & 3)) << 4);
}
__device__ __forceinline__ uint32_t swzB(uint32_t row, uint32_t ch){
    return row * 256 + ((ch ^ (row & 7)) << 4);
}

#define STAGE 32768u        // 4 parts x 8KB per stage (BK=32)
#define NSTAGE 3
#define SMEM_DYN (STAGE*NSTAGE)   // 98304 -> 2 CTAs/SM

// ---------------------------------------------------------------------------
// bf16x3 warp-MMA GEMM, 3-stage cp.async, BK=32, term-major issue order.
// ---------------------------------------------------------------------------
template<int EPI, bool BT>
__device__ void gemm_mma(
    const __nv_bfloat16* __restrict__ Ah, const __nv_bfloat16* __restrict__ Al, int lda,
    const __nv_bfloat16* __restrict__ Bh, const __nv_bfloat16* __restrict__ Bl, int ldb,
    int kCount, int m0, int n0, float scale,
    float* __restrict__ Cf, int ldc,
    __nv_bfloat16* __restrict__ Oh, __nv_bfloat16* __restrict__ Ol, int orow)
{
    extern __shared__ char sm[];
    const int tid = threadIdx.x, lane = tid & 31, wid = tid >> 5;
    const int wm = wid & 3, wn = wid >> 2;
    const int g = lane >> 2, t4 = lane & 3;
    const uint32_t sbase = smem_u32(sm);

    const int mtx = lane >> 3, ri = lane & 7;
    const int lrow = ((mtx & 1) << 3) + ri;
    const int lkh  = mtx >> 1;
    const int brow = ((lane >> 4) << 3) + ri;
    const int bchh = (lane >> 3) & 1;

    const __nv_bfloat16* Ap[2] = {Ah, Al};
    const __nv_bfloat16* Bp[2] = {Bh, Bl};

    float acc[64];
#pragma unroll
    for (int i = 0; i < 64; i++) acc[i] = 0.f;

    const int nk = kCount >> 5;

    auto load_chunk = [&](int kc){
        const uint32_t sb = sbase + (uint32_t)(kc % NSTAGE) * STAGE;
        const int k0 = kc << 5;
#pragma unroll
        for (int p = 0; p < 2; p++)
#pragma unroll
            for (int i = 0; i < 2; i++) {
                int lin = tid + i * 256;
                int r = lin >> 2, ch = lin & 3;
                cp16(sb + p * 8192 + swzA(r, ch),
                     Ap[p] + (size_t)(m0 + r) * lda + k0 + ch * 8);
            }
        if (BT) {
#pragma unroll
            for (int p = 0; p < 2; p++)
#pragma unroll
                for (int i = 0; i < 2; i++) {
                    int lin = tid + i * 256;
                    int r = lin >> 2, ch = lin & 3;
                    cp16(sb + 16384 + p * 8192 + swzA(r, ch),
                         Bp[p] + (size_t)(n0 + r) * ldb + k0 + ch * 8);
                }
        } else {
#pragma unroll
            for (int p = 0; p < 2; p++)
#pragma unroll
                for (int i = 0; i < 2; i++) {
                    int lin = tid + i * 256;
                    int r = lin >> 4, ch = lin & 15;
                    cp16(sb + 16384 + p * 8192 + swzB(r, ch),
                         Bp[p] + (size_t)(k0 + r) * ldb + n0 + ch * 8);
                }
        }
    };

    load_chunk(0);            CP_COMMIT();
    if (nk > 1) load_chunk(1);
    CP_COMMIT();

    for (int kc = 0; kc < nk; kc++) {
        if (kc + 2 < nk) load_chunk(kc + 2);
        CP_COMMIT();
        cp_wait<2>();
        __syncthreads();

        const uint32_t cb = sbase + (uint32_t)(kc % NSTAGE) * STAGE;
#pragma unroll
        for (int kk = 0; kk < 2; kk++) {
            const int ch = kk * 2 + lkh;
            uint32_t aH[8], aL[8];
#pragma unroll
            for (int s = 0; s < 2; s++) {
                uint32_t off = swzA((uint32_t)(wm * 32 + s * 16 + lrow), ch);
                ldsm4(aH + s * 4, cb + off);
                ldsm4(aL + s * 4, cb + 8192 + off);
            }
#pragma unroll
            for (int nbp = 0; nbp < 2; nbp++) {
                uint32_t bh[8], bl[8];
#pragma unroll
                for (int q = 0; q < 2; q++) {
                    int nb = nbp * 2 + q;
                    if (BT) {
                        uint32_t off = swzA((uint32_t)(wn * 64 + nb * 16 + lrow), ch);
                        ldsm4(bh + q * 4, cb + 16384 + off);
                        ldsm4(bl + q * 4, cb + 24576 + off);
                    } else {
                        uint32_t off = swzB((uint32_t)(kk * 16 + brow),
                                            (uint32_t)(wn * 8 + nb * 2 + bchh));
                        ldsm4t(bh + q * 4, cb + 16384 + off);
                        ldsm4t(bl + q * 4, cb + 24576 + off);
                    }
                }
#pragma unroll
                for (int t = 0; t < 3; t++) {
#pragma unroll
                    for (int q = 0; q < 2; q++) {
#pragma unroll
                        for (int mi = 0; mi < 2; mi++) {
#pragma unroll
                            for (int sub = 0; sub < 2; sub++) {
                                int nb = nbp * 2 + q;
                                float* c = acc + (mi * 8 + nb * 2 + sub) * 4;
                                const uint32_t* a = (t == 2) ? (aL + mi * 4) : (aH + mi * 4);
                                const uint32_t* b = (t == 1) ? (bl + q * 4) : (bh + q * 4);
                                mma16816(c, a, b[sub], b[sub + 2]);
                            }
                        }
                    }
                }
            }
        }
        __syncthreads();
    }

    // ---- epilogue straight from registers
#pragma unroll
    for (int mi = 0; mi < 2; mi++) {
#pragma unroll
        for (int nbi = 0; nbi < 8; nbi++) {
            const float* c = acc + (mi * 8 + nbi) * 4;
            int rl = wm * 32 + mi * 16 + g;
            int cl = wn * 64 + nbi * 8 + 2 * t4;
            if (EPI <= 1) {
                int gr0 = m0 + rl, gc = n0 + cl;
                float v0 = c[0] * scale, v1 = c[1] * scale;
                float v2 = c[2] * scale, v3 = c[3] * scale;
                if (EPI == 0) {
                    if (gc     > gr0)     v0 = -CUDART_INF_F;
                    if (gc + 1 > gr0)     v1 = -CUDART_INF_F;
                    if (gc     > gr0 + 8) v2 = -CUDART_INF_F;
                    if (gc + 1 > gr0 + 8) v3 = -CUDART_INF_F;
                }
                *reinterpret_cast<float2*>(Cf + (size_t)gr0 * ldc + gc)       = make_float2(v0, v1);
                *reinterpret_cast<float2*>(Cf + (size_t)(gr0 + 8) * ldc + gc) = make_float2(v2, v3);
            } else {
                __nv_bfloat16 h0 = __float2bfloat16(c[0]);
                __nv_bfloat16 h1 = __float2bfloat16(c[1]);
                __nv_bfloat16 h2 = __float2bfloat16(c[2]);
                __nv_bfloat16 h3 = __float2bfloat16(c[3]);
                __nv_bfloat16 l0 = __float2bfloat16(c[0] - __bfloat162float(h0));
                __nv_bfloat16 l1 = __float2bfloat16(c[1] - __bfloat162float(h1));
                __nv_bfloat16 l2 = __float2bfloat16(c[2] - __bfloat162float(h2));
                __nv_bfloat16 l3 = __float2bfloat16(c[3] - __bfloat162float(h3));
                size_t gm = (size_t)(m0 + rl);
                size_t o0 = gm * orow + cl, o1 = o0 + (size_t)8 * orow;
                *reinterpret_cast<__nv_bfloat162*>(Oh + o0) = __nv_bfloat162(h0, h1);
                *reinterpret_cast<__nv_bfloat162*>(Ol + o0) = __nv_bfloat162(l0, l1);
                *reinterpret_cast<__nv_bfloat162*>(Oh + o1) = __nv_bfloat162(h2, h3);
                *reinterpret_cast<__nv_bfloat162*>(Ol + o1) = __nv_bfloat162(l2, l3);
            }
        }
    }
}

// ---------------------------------------------------------------------------
__global__ void __launch_bounds__(256) k_split_all(
    const float* __restrict__ x,  const float* __restrict__ Wq,
    const float* __restrict__ Wk, const float* __restrict__ Wv,
    const float* __restrict__ Wu)
{
    const int z = blockIdx.y;
    const float* s;
    __nv_bfloat16 *h, *l;
    switch (z) {
        case 0: s = x;  h = g_xh;  l = g_xl;  break;
        case 1: s = Wq; h = g_wqh; l = g_wql; break;
        case 2: s = Wk; h = g_wkh; l = g_wkl; break;
        case 3: s = Wv; h = g_wvh; l = g_wvl; break;
        default: s = Wu; h = g_wuh; l = g_wul; break;
    }
    int i = blockIdx.x * blockDim.x + threadIdx.x;
    float4 v = reinterpret_cast<const float4*>(s)[i];
    __nv_bfloat16 h0=__float2bfloat16(v.x), h1=__float2bfloat16(v.y),
                  h2=__float2bfloat16(v.z), h3=__float2bfloat16(v.w);
    __nv_bfloat16 l0=__float2bfloat16(v.x-__bfloat162float(h0)),
                  l1=__float2bfloat16(v.y-__bfloat162float(h1)),
                  l2=__float2bfloat16(v.z-__bfloat162float(h2)),
                  l3=__float2bfloat16(v.w-__bfloat162float(h3));
    uint2 hv = make_uint2((uint32_t)__bfloat16_as_ushort(h0)|((uint32_t)__bfloat16_as_ushort(h1)<<16),
                          (uint32_t)__bfloat16_as_ushort(h2)|((uint32_t)__bfloat16_as_ushort(h3)<<16));
    uint2 lv = make_uint2((uint32_t)__bfloat16_as_ushort(l0)|((uint32_t)__bfloat16_as_ushort(l1)<<16),
                          (uint32_t)__bfloat16_as_ushort(l2)|((uint32_t)__bfloat16_as_ushort(l3)<<16));
    reinterpret_cast<uint2*>(h)[i] = hv;
    reinterpret_cast<uint2*>(l)[i] = lv;
}

__global__ void __launch_bounds__(256, 2) k_qkv_mma(void)
{
    int n0 = blockIdx.x * 128, m0 = blockIdx.y * 128, z = blockIdx.z;
    int b = m0 >> 11, h = n0 >> 9, e0 = n0 & 511;
    const __nv_bfloat16 *Wh, *Wl;
    __nv_bfloat16 *OH, *OL;
    if (z == 0)      { Wh = g_wqh; Wl = g_wql; OH = g_qh; OL = g_ql; }
    else if (z == 1) { Wh = g_wkh; Wl = g_wkl; OH = g_kh; OL = g_kl; }
    else             { Wh = g_wvh; Wl = g_wvl; OH = g_vh; OL = g_vl; }
    size_t base = ((size_t)(b * HH + h) * SS) * DK + e0 - (size_t)(b * SS) * DK;
    gemm_mma<2, true>(g_xh, g_xl, 512, Wh, Wl, 512, 512, m0, n0, 1.f,
                      nullptr, 0, OH + base, OL + base, 512);
}

// Triangular grid: blockIdx.x in [0,136) -> (row, col) of lower triangle.
__global__ void __launch_bounds__(256, 2) k_scores_mma(void)
{
    int t = blockIdx.x, bh = blockIdx.z;
    int r = (int)((sqrtf(8.f * t + 1.f) - 1.f) * 0.5f);
    while ((r + 1) * (r + 2) / 2 <= t) r++;
    while (r * (r + 1) / 2 > t) r--;
    int c = t - r * (r + 1) / 2;
    int m0 = r * 128, n0 = c * 128;
    float* Cf = g_s + (size_t)bh * SS * SS;
    size_t ob = (size_t)bh * SS * DK;
    gemm_mma<0, true>(g_qh + ob, g_ql + ob, 512, g_kh + ob, g_kl + ob, 512,
                      512, m0, n0, 0.04419417382415922f, Cf, SS, nullptr, nullptr, 0);
}

__global__ void __launch_bounds__(256) k_softmax(void)
{
    int row  = blockIdx.x * 8 + (threadIdx.x >> 5);
    int lane = threadIdx.x & 31;
    int r    = row & (SS - 1);
    int rt   = r >> 7;
    const float4* p = reinterpret_cast<const float4*>(g_s + (size_t)row * SS);
    uint2* ph = reinterpret_cast<uint2*>(g_ph + (size_t)row * SS);
    uint2* pl = reinterpret_cast<uint2*>(g_pl + (size_t)row * SS);

    float4 v[16];
    float mx = -CUDART_INF_F;
#pragma unroll
    for (int i = 0; i < 16; i++) {
        if (i <= rt) {
            v[i] = p[lane + i * 32];
            mx = fmaxf(mx, fmaxf(fmaxf(v[i].x, v[i].y), fmaxf(v[i].z, v[i].w)));
        }
    }
#pragma unroll
    for (int o = 16; o; o >>= 1) mx = fmaxf(mx, __shfl_xor_sync(0xffffffffu, mx, o));
    float sum = 0.0f;
#pragma unroll
    for (int i = 0; i < 16; i++) {
        if (i > rt) continue;
        v[i].x = __expf(v[i].x - mx); v[i].y = __expf(v[i].y - mx);
        v[i].z = __expf(v[i].z - mx); v[i].w = __expf(v[i].w - mx);
        sum += (v[i].x + v[i].y) + (v[i].z + v[i].w);
    }
#pragma unroll
    for (int o = 16; o; o >>= 1) sum += __shfl_xor_sync(0xffffffffu, sum, o);
    float inv = 1.0f / sum;
#pragma unroll
    for (int i = 0; i < 16; i++) {
        if (i > rt) continue;
        float a0 = v[i].x*inv, a1 = v[i].y*inv, a2 = v[i].z*inv, a3 = v[i].w*inv;
        __nv_bfloat16 h0=__float2bfloat16(a0), h1=__float2bfloat16(a1),
                      h2=__float2bfloat16(a2), h3=__float2bfloat16(a3);
        __nv_bfloat16 l0=__float2bfloat16(a0-__bfloat162float(h0)),
                      l1=__float2bfloat16(a1-__bfloat162float(h1)),
                      l2=__float2bfloat16(a2-__bfloat162float(h2)),
                      l3=__float2bfloat16(a3-__bfloat162float(h3));
        ph[lane + i*32] = make_uint2(
            (uint32_t)__bfloat16_as_ushort(h0)|((uint32_t)__bfloat16_as_ushort(h1)<<16),
            (uint32_t)__bfloat16_as_ushort(h2)|((uint32_t)__bfloat16_as_ushort(h3)<<16));
        pl[lane + i*32] = make_uint2(
            (uint32_t)__bfloat16_as_ushort(l0)|((uint32_t)__bfloat16_as_ushort(l1)<<16),
            (uint32_t)__bfloat16_as_ushort(l2)|((uint32_t)__bfloat16_as_ushort(l3)<<16));
    }
}

__global__ void __launch_bounds__(256, 2) k_pv_mma(void)
{
    int bh = blockIdx.z, b = bh >> 3, h = bh & 7;
    int m0 = blockIdx.y * 128, n0 = blockIdx.x * 128;
    const __nv_bfloat16* Ah = g_ph + (size_t)bh * SS * SS;
    const __nv_bfloat16* Al = g_pl + (size_t)bh * SS * SS;
    const __nv_bfloat16* Bh = g_vh + (size_t)bh * SS * DK;
    const __nv_bfloat16* Bl = g_vl + (size_t)bh * SS * DK;
    size_t base = (size_t)b * SS * 4096 + h * 512 + n0;
    gemm_mma<2, false>(Ah, Al, SS, Bh, Bl, 512, m0 + 128, m0, n0, 1.f,
                       nullptr, 0, g_hoh + base, g_hol + base, 4096);
}

// out GEMM k-split into 4 slices of K=1024; fp32 partials to g_op[slice].
__global__ void __launch_bounds__(256, 2) k_out_mma(void)
{
    int m0 = blockIdx.y * 128, n0 = blockIdx.x * 128, sl = blockIdx.z;
    int koff = sl * 1024;
    gemm_mma<1, true>(g_hoh + koff, g_hol + koff, 4096,
                      g_wuh + koff, g_wul + koff, 4096,
                      1024, m0, n0, 1.f,
                      g_op[sl], 512, nullptr, nullptr, 0);
}

__global__ void __launch_bounds__(256) k_reduce_out(float* __restrict__ out)
{
    int i = blockIdx.x * blockDim.x + threadIdx.x;   // float4 index
    float4 a = reinterpret_cast<const float4*>(g_op[0])[i];
    float4 b = reinterpret_cast<const float4*>(g_op[1])[i];
    float4 c = reinterpret_cast<const float4*>(g_op[2])[i];
    float4 d = reinterpret_cast<const float4*>(g_op[3])[i];
    float4 o;
    o.x = (a.x + b.x) + (c.x + d.x);
    o.y = (a.y + b.y) + (c.y + d.y);
    o.z = (a.z + b.z) + (c.z + d.z);
    o.w = (a.w + b.w) + (c.w + d.w);
    reinterpret_cast<float4*>(out)[i] = o;
}

// ---------------------------------------------------------------------------
extern "C" void kernel_launch(void* const* d_in, const int* in_sizes, int n_in,
                              void* d_out, int out_size)
{
    const float* x  = (const float*)d_in[0];
    const float* Wq = (const float*)d_in[1];
    const float* Wk = (const float*)d_in[2];
    const float* Wv = (const float*)d_in[3];
    const float* Wu = (const float*)d_in[4];
    float* out = (float*)d_out;

    cudaFuncSetAttribute(k_qkv_mma,    cudaFuncAttributeMaxDynamicSharedMemorySize, SMEM_DYN);
    cudaFuncSetAttribute(k_scores_mma, cudaFuncAttributeMaxDynamicSharedMemorySize, SMEM_DYN);
    cudaFuncSetAttribute(k_pv_mma,     cudaFuncAttributeMaxDynamicSharedMemorySize, SMEM_DYN);
    cudaFuncSetAttribute(k_out_mma,    cudaFuncAttributeMaxDynamicSharedMemorySize, SMEM_DYN);

    const int n4 = TT * DK / 4;
    k_split_all <<<dim3(n4 / 256, 5), 256>>>(x, Wq, Wk, Wv, Wu);

    k_qkv_mma   <<<dim3(32, 32, 3),  256, SMEM_DYN>>>();
    k_scores_mma<<<dim3(136, 1, NH), 256, SMEM_DYN>>>();
    k_softmax   <<<NH * SS / 8, 256>>>();
    k_pv_mma    <<<dim3(4, 16, NH),  256, SMEM_DYN>>>();
    k_out_mma   <<<dim3(4, 32, 4),   256, SMEM_DYN>>>();
    k_reduce_out<<<(TT * 512 / 4) / 256, 256>>>(out);
}

// round 12
// speedup vs baseline: 1.7071x; 1.0197x over previous
#include <cuda_runtime.h>
#include <cuda_bf16.h>
#include <cuda_fp16.h>
#include <math_constants.h>
#include <cstdint>

#define BB 2
#define SS 2048
#define HH 8
#define DK 512
#define TT (BB*SS)      // 4096 tokens
#define NH (BB*HH)      // 16 (b,h) pairs

// ---------------- static device scratch (no allocs allowed) ----------------
__device__ __nv_bfloat16 g_xh[TT*DK],  g_xl[TT*DK];
__device__ __nv_bfloat16 g_wqh[4096*512], g_wql[4096*512];
__device__ __nv_bfloat16 g_wkh[4096*512], g_wkl[4096*512];
__device__ __nv_bfloat16 g_wvh[4096*512], g_wvl[4096*512];
__device__ __nv_bfloat16 g_wuh[512*4096], g_wul[512*4096];   // fp16 bits (out gemm)
__device__ __nv_bfloat16 g_qh[NH*SS*DK], g_ql[NH*SS*DK];
__device__ __nv_bfloat16 g_kh[NH*SS*DK], g_kl[NH*SS*DK];
__device__ __nv_bfloat16 g_vh[NH*SS*DK], g_vl[NH*SS*DK];
__device__ float         g_s [(size_t)NH*SS*SS];
__device__ __nv_bfloat16 g_ph[(size_t)NH*SS*SS], g_pl[(size_t)NH*SS*SS];
__device__ __nv_bfloat16 g_hoh[(size_t)TT*4096], g_hol[(size_t)TT*4096]; // fp16 bits
__device__ float         g_op[4][(size_t)TT*512];

// ---------------- helpers ----------------
__device__ __forceinline__ uint32_t smem_u32(const void* p){
    uint32_t a; asm("{ .reg .u64 t; cvta.to.shared.u64 t, %1; cvt.u32.u64 %0, t; }":"=r"(a):"l"(p)); return a;
}
__device__ __forceinline__ void ldsm4(uint32_t* r, uint32_t addr){
    asm volatile("ldmatrix.sync.aligned.m8n8.x4.shared.b16 {%0,%1,%2,%3}, [%4];"
        : "=r"(r[0]),"=r"(r[1]),"=r"(r[2]),"=r"(r[3]) : "r"(addr));
}
__device__ __forceinline__ void ldsm4t(uint32_t* r, uint32_t addr){
    asm volatile("ldmatrix.sync.aligned.m8n8.x4.trans.shared.b16 {%0,%1,%2,%3}, [%4];"
        : "=r"(r[0]),"=r"(r[1]),"=r"(r[2]),"=r"(r[3]) : "r"(addr));
}
__device__ __forceinline__ void mma_bf16(float* c, const uint32_t* a, uint32_t b0, uint32_t b1){
    asm volatile("mma.sync.aligned.m16n8k16.row.col.f32.bf16.bf16.f32 "
        "{%0,%1,%2,%3}, {%4,%5,%6,%7}, {%8,%9}, {%0,%1,%2,%3};"
        : "+f"(c[0]),"+f"(c[1]),"+f"(c[2]),"+f"(c[3])
        : "r"(a[0]),"r"(a[1]),"r"(a[2]),"r"(a[3]), "r"(b0),"r"(b1));
}
__device__ __forceinline__ void mma_f16(float* c, const uint32_t* a, uint32_t b0, uint32_t b1){
    asm volatile("mma.sync.aligned.m16n8k16.row.col.f32.f16.f16.f32 "
        "{%0,%1,%2,%3}, {%4,%5,%6,%7}, {%8,%9}, {%0,%1,%2,%3};"
        : "+f"(c[0]),"+f"(c[1]),"+f"(c[2]),"+f"(c[3])
        : "r"(a[0]),"r"(a[1]),"r"(a[2]),"r"(a[3]), "r"(b0),"r"(b1));
}
__device__ __forceinline__ void cp16(uint32_t dst, const void* src){
    asm volatile("cp.async.cg.shared.global [%0], [%1], 16;" :: "r"(dst), "l"(src) : "memory");
}
#define CP_COMMIT() asm volatile("cp.async.commit_group;" ::: "memory")
template<int N> __device__ __forceinline__ void cp_wait(){
    asm volatile("cp.async.wait_group %0;" :: "n"(N) : "memory");
}
__device__ __forceinline__ uint32_t swzA(uint32_t row, uint32_t ch){
    return row * 64 + ((ch ^ ((row >> 1) & 3)) << 4);
}
__device__ __forceinline__ uint32_t swzB(uint32_t row, uint32_t ch){
    return row * 256 + ((ch ^ (row & 7)) << 4);
}

#define STAGE 32768u
#define NSTAGE 3
#define SMEM_DYN (STAGE*NSTAGE)   // 98304 -> 2 CTAs/SM

// ---------------------------------------------------------------------------
// Split-precision warp-MMA GEMM, 3-stage cp.async, BK=32, term-major.
// TERMS==3: bf16x3 (Ah·Bh + Ah·Bl + Al·Bh).  TERMS==2: fp16x2 ((Ah+Al)·Bh).
// EPI: 0 fp32+mask | 1 fp32 | 2 split-bf16 out | 3 split-fp16 out
// ---------------------------------------------------------------------------
template<int EPI, bool BT, int TERMS>
__device__ void gemm_mma(
    const __nv_bfloat16* __restrict__ Ah, const __nv_bfloat16* __restrict__ Al, int lda,
    const __nv_bfloat16* __restrict__ Bh, const __nv_bfloat16* __restrict__ Bl, int ldb,
    int kCount, int m0, int n0, float scale,
    float* __restrict__ Cf, int ldc,
    __nv_bfloat16* __restrict__ Oh, __nv_bfloat16* __restrict__ Ol, int orow)
{
    extern __shared__ char sm[];
    const int tid = threadIdx.x, lane = tid & 31, wid = tid >> 5;
    const int wm = wid & 3, wn = wid >> 2;
    const int g = lane >> 2, t4 = lane & 3;
    const uint32_t sbase = smem_u32(sm);

    const int mtx = lane >> 3, ri = lane & 7;
    const int lrow = ((mtx & 1) << 3) + ri;
    const int lkh  = mtx >> 1;
    const int brow = ((lane >> 4) << 3) + ri;
    const int bchh = (lane >> 3) & 1;

    const __nv_bfloat16* Ap[2] = {Ah, Al};
    const __nv_bfloat16* Bp[2] = {Bh, Bl};

    float acc[64];
#pragma unroll
    for (int i = 0; i < 64; i++) acc[i] = 0.f;

    const int nk = kCount >> 5;

    auto load_chunk = [&](int kc){
        const uint32_t sb = sbase + (uint32_t)(kc % NSTAGE) * STAGE;
        const int k0 = kc << 5;
#pragma unroll
        for (int p = 0; p < 2; p++)
#pragma unroll
            for (int i = 0; i < 2; i++) {
                int lin = tid + i * 256;
                int r = lin >> 2, ch = lin & 3;
                cp16(sb + p * 8192 + swzA(r, ch),
                     Ap[p] + (size_t)(m0 + r) * lda + k0 + ch * 8);
            }
        if (BT) {
#pragma unroll
            for (int p = 0; p < (TERMS == 2 ? 1 : 2); p++)
#pragma unroll
                for (int i = 0; i < 2; i++) {
                    int lin = tid + i * 256;
                    int r = lin >> 2, ch = lin & 3;
                    cp16(sb + 16384 + p * 8192 + swzA(r, ch),
                         Bp[p] + (size_t)(n0 + r) * ldb + k0 + ch * 8);
                }
        } else {
#pragma unroll
            for (int p = 0; p < (TERMS == 2 ? 1 : 2); p++)
#pragma unroll
                for (int i = 0; i < 2; i++) {
                    int lin = tid + i * 256;
                    int r = lin >> 4, ch = lin & 15;
                    cp16(sb + 16384 + p * 8192 + swzB(r, ch),
                         Bp[p] + (size_t)(k0 + r) * ldb + n0 + ch * 8);
                }
        }
    };

    load_chunk(0);            CP_COMMIT();
    if (nk > 1) load_chunk(1);
    CP_COMMIT();

    for (int kc = 0; kc < nk; kc++) {
        if (kc + 2 < nk) load_chunk(kc + 2);
        CP_COMMIT();
        cp_wait<2>();
        __syncthreads();

        const uint32_t cb = sbase + (uint32_t)(kc % NSTAGE) * STAGE;
#pragma unroll
        for (int kk = 0; kk < 2; kk++) {
            const int ch = kk * 2 + lkh;
            uint32_t aH[8], aL[8];
#pragma unroll
            for (int s = 0; s < 2; s++) {
                uint32_t off = swzA((uint32_t)(wm * 32 + s * 16 + lrow), ch);
                ldsm4(aH + s * 4, cb + off);
                ldsm4(aL + s * 4, cb + 8192 + off);
            }
#pragma unroll
            for (int nbp = 0; nbp < 2; nbp++) {
                uint32_t bh[8], bl[8];
#pragma unroll
                for (int q = 0; q < 2; q++) {
                    int nb = nbp * 2 + q;
                    if (BT) {
                        uint32_t off = swzA((uint32_t)(wn * 64 + nb * 16 + lrow), ch);
                        ldsm4(bh + q * 4, cb + 16384 + off);
                        if (TERMS == 3) ldsm4(bl + q * 4, cb + 24576 + off);
                    } else {
                        uint32_t off = swzB((uint32_t)(kk * 16 + brow),
                                            (uint32_t)(wn * 8 + nb * 2 + bchh));
                        ldsm4t(bh + q * 4, cb + 16384 + off);
                        if (TERMS == 3) ldsm4t(bl + q * 4, cb + 24576 + off);
                    }
                }
#pragma unroll
                for (int t = 0; t < TERMS; t++) {
#pragma unroll
                    for (int q = 0; q < 2; q++) {
#pragma unroll
                        for (int mi = 0; mi < 2; mi++) {
#pragma unroll
                            for (int sub = 0; sub < 2; sub++) {
                                int nb = nbp * 2 + q;
                                float* c = acc + (mi * 8 + nb * 2 + sub) * 4;
                                if (TERMS == 3) {
                                    const uint32_t* a = (t == 2) ? (aL + mi * 4) : (aH + mi * 4);
                                    const uint32_t* b = (t == 1) ? (bl + q * 4) : (bh + q * 4);
                                    mma_bf16(c, a, b[sub], b[sub + 2]);
                                } else {
                                    const uint32_t* a = (t == 1) ? (aL + mi * 4) : (aH + mi * 4);
                                    const uint32_t* b = bh + q * 4;
                                    mma_f16(c, a, b[sub], b[sub + 2]);
                                }
                            }
                        }
                    }
                }
            }
        }
        __syncthreads();
    }

    // ---- epilogue
#pragma unroll
    for (int mi = 0; mi < 2; mi++) {
#pragma unroll
        for (int nbi = 0; nbi < 8; nbi++) {
            const float* c = acc + (mi * 8 + nbi) * 4;
            int rl = wm * 32 + mi * 16 + g;
            int cl = wn * 64 + nbi * 8 + 2 * t4;
            if (EPI <= 1) {
                int gr0 = m0 + rl, gc = n0 + cl;
                float v0 = c[0] * scale, v1 = c[1] * scale;
                float v2 = c[2] * scale, v3 = c[3] * scale;
                if (EPI == 0) {
                    if (gc     > gr0)     v0 = -CUDART_INF_F;
                    if (gc + 1 > gr0)     v1 = -CUDART_INF_F;
                    if (gc     > gr0 + 8) v2 = -CUDART_INF_F;
                    if (gc + 1 > gr0 + 8) v3 = -CUDART_INF_F;
                }
                *reinterpret_cast<float2*>(Cf + (size_t)gr0 * ldc + gc)       = make_float2(v0, v1);
                *reinterpret_cast<float2*>(Cf + (size_t)(gr0 + 8) * ldc + gc) = make_float2(v2, v3);
            } else if (EPI == 2) {
                __nv_bfloat16 h0 = __float2bfloat16(c[0]);
                __nv_bfloat16 h1 = __float2bfloat16(c[1]);
                __nv_bfloat16 h2 = __float2bfloat16(c[2]);
                __nv_bfloat16 h3 = __float2bfloat16(c[3]);
                __nv_bfloat16 l0 = __float2bfloat16(c[0] - __bfloat162float(h0));
                __nv_bfloat16 l1 = __float2bfloat16(c[1] - __bfloat162float(h1));
                __nv_bfloat16 l2 = __float2bfloat16(c[2] - __bfloat162float(h2));
                __nv_bfloat16 l3 = __float2bfloat16(c[3] - __bfloat162float(h3));
                size_t gm = (size_t)(m0 + rl);
                size_t o0 = gm * orow + cl, o1 = o0 + (size_t)8 * orow;
                *reinterpret_cast<__nv_bfloat162*>(Oh + o0) = __nv_bfloat162(h0, h1);
                *reinterpret_cast<__nv_bfloat162*>(Ol + o0) = __nv_bfloat162(l0, l1);
                *reinterpret_cast<__nv_bfloat162*>(Oh + o1) = __nv_bfloat162(h2, h3);
                *reinterpret_cast<__nv_bfloat162*>(Ol + o1) = __nv_bfloat162(l2, l3);
            } else {
                __half h0 = __float2half(c[0]);
                __half h1 = __float2half(c[1]);
                __half h2 = __float2half(c[2]);
                __half h3 = __float2half(c[3]);
                __half l0 = __float2half(c[0] - __half2float(h0));
                __half l1 = __float2half(c[1] - __half2float(h1));
                __half l2 = __float2half(c[2] - __half2float(h2));
                __half l3 = __float2half(c[3] - __half2float(h3));
                size_t gm = (size_t)(m0 + rl);
                size_t o0 = gm * orow + cl, o1 = o0 + (size_t)8 * orow;
                __half* OH = reinterpret_cast<__half*>(Oh);
                __half* OL = reinterpret_cast<__half*>(Ol);
                *reinterpret_cast<__half2*>(OH + o0) = __half2(h0, h1);
                *reinterpret_cast<__half2*>(OL + o0) = __half2(l0, l1);
                *reinterpret_cast<__half2*>(OH + o1) = __half2(h2, h3);
                *reinterpret_cast<__half2*>(OL + o1) = __half2(l2, l3);
            }
        }
    }
}

// ---------------------------------------------------------------------------
__global__ void k_dummy(void) {}   // shifts ncu capture slot (4th launch = scores)

__global__ void __launch_bounds__(256) k_split_all(
    const float* __restrict__ x,  const float* __restrict__ Wq,
    const float* __restrict__ Wk, const float* __restrict__ Wv,
    const float* __restrict__ Wu)
{
    const int z = blockIdx.y;
    const float* s;
    __nv_bfloat16 *h, *l;
    switch (z) {
        case 0: s = x;  h = g_xh;  l = g_xl;  break;
        case 1: s = Wq; h = g_wqh; l = g_wql; break;
        case 2: s = Wk; h = g_wkh; l = g_wkl; break;
        case 3: s = Wv; h = g_wvh; l = g_wvl; break;
        default: s = Wu; h = g_wuh; l = g_wul; break;
    }
    int i = blockIdx.x * blockDim.x + threadIdx.x;
    float4 v = reinterpret_cast<const float4*>(s)[i];
    if (z == 4) {
        // fp16 split for the 2-term out gemm
        __half h0=__float2half(v.x), h1=__float2half(v.y),
               h2=__float2half(v.z), h3=__float2half(v.w);
        __half l0=__float2half(v.x-__half2float(h0)),
               l1=__float2half(v.y-__half2float(h1)),
               l2=__float2half(v.z-__half2float(h2)),
               l3=__float2half(v.w-__half2float(h3));
        uint2 hv = make_uint2((uint32_t)__half_as_ushort(h0)|((uint32_t)__half_as_ushort(h1)<<16),
                              (uint32_t)__half_as_ushort(h2)|((uint32_t)__half_as_ushort(h3)<<16));
        uint2 lv = make_uint2((uint32_t)__half_as_ushort(l0)|((uint32_t)__half_as_ushort(l1)<<16),
                              (uint32_t)__half_as_ushort(l2)|((uint32_t)__half_as_ushort(l3)<<16));
        reinterpret_cast<uint2*>(h)[i] = hv;
        reinterpret_cast<uint2*>(l)[i] = lv;
        return;
    }
    __nv_bfloat16 h0=__float2bfloat16(v.x), h1=__float2bfloat16(v.y),
                  h2=__float2bfloat16(v.z), h3=__float2bfloat16(v.w);
    __nv_bfloat16 l0=__float2bfloat16(v.x-__bfloat162float(h0)),
                  l1=__float2bfloat16(v.y-__bfloat162float(h1)),
                  l2=__float2bfloat16(v.z-__bfloat162float(h2)),
                  l3=__float2bfloat16(v.w-__bfloat162float(h3));
    uint2 hv = make_uint2((uint32_t)__bfloat16_as_ushort(h0)|((uint32_t)__bfloat16_as_ushort(h1)<<16),
                          (uint32_t)__bfloat16_as_ushort(h2)|((uint32_t)__bfloat16_as_ushort(h3)<<16));
    uint2 lv = make_uint2((uint32_t)__bfloat16_as_ushort(l0)|((uint32_t)__bfloat16_as_ushort(l1)<<16),
                          (uint32_t)__bfloat16_as_ushort(l2)|((uint32_t)__bfloat16_as_ushort(l3)<<16));
    reinterpret_cast<uint2*>(h)[i] = hv;
    reinterpret_cast<uint2*>(l)[i] = lv;
}

__global__ void __launch_bounds__(256, 2) k_qkv_mma(void)
{
    int n0 = blockIdx.x * 128, m0 = blockIdx.y * 128, z = blockIdx.z;
    int b = m0 >> 11, h = n0 >> 9, e0 = n0 & 511;
    const __nv_bfloat16 *Wh, *Wl;
    __nv_bfloat16 *OH, *OL;
    if (z == 0)      { Wh = g_wqh; Wl = g_wql; OH = g_qh; OL = g_ql; }
    else if (z == 1) { Wh = g_wkh; Wl = g_wkl; OH = g_kh; OL = g_kl; }
    else             { Wh = g_wvh; Wl = g_wvl; OH = g_vh; OL = g_vl; }
    size_t base = ((size_t)(b * HH + h) * SS) * DK + e0 - (size_t)(b * SS) * DK;
    gemm_mma<2, true, 3>(g_xh, g_xl, 512, Wh, Wl, 512, 512, m0, n0, 1.f,
                         nullptr, 0, OH + base, OL + base, 512);
}

__global__ void __launch_bounds__(256, 2) k_scores_mma(void)
{
    int t = blockIdx.x, bh = blockIdx.z;
    int r = (int)((sqrtf(8.f * t + 1.f) - 1.f) * 0.5f);
    while ((r + 1) * (r + 2) / 2 <= t) r++;
    while (r * (r + 1) / 2 > t) r--;
    int c = t - r * (r + 1) / 2;
    int m0 = r * 128, n0 = c * 128;
    float* Cf = g_s + (size_t)bh * SS * SS;
    size_t ob = (size_t)bh * SS * DK;
    gemm_mma<0, true, 3>(g_qh + ob, g_ql + ob, 512, g_kh + ob, g_kl + ob, 512,
                         512, m0, n0, 0.04419417382415922f, Cf, SS, nullptr, nullptr, 0);
}

__global__ void __launch_bounds__(256) k_softmax(void)
{
    int row  = blockIdx.x * 8 + (threadIdx.x >> 5);
    int lane = threadIdx.x & 31;
    int r    = row & (SS - 1);
    int rt   = r >> 7;
    const float4* p = reinterpret_cast<const float4*>(g_s + (size_t)row * SS);
    uint2* ph = reinterpret_cast<uint2*>(g_ph + (size_t)row * SS);
    uint2* pl = reinterpret_cast<uint2*>(g_pl + (size_t)row * SS);

    float4 v[16];
    float mx = -CUDART_INF_F;
#pragma unroll
    for (int i = 0; i < 16; i++) {
        if (i <= rt) {
            v[i] = p[lane + i * 32];
            mx = fmaxf(mx, fmaxf(fmaxf(v[i].x, v[i].y), fmaxf(v[i].z, v[i].w)));
        }
    }
#pragma unroll
    for (int o = 16; o; o >>= 1) mx = fmaxf(mx, __shfl_xor_sync(0xffffffffu, mx, o));
    float sum = 0.0f;
#pragma unroll
    for (int i = 0; i < 16; i++) {
        if (i > rt) continue;
        v[i].x = __expf(v[i].x - mx); v[i].y = __expf(v[i].y - mx);
        v[i].z = __expf(v[i].z - mx); v[i].w = __expf(v[i].w - mx);
        sum += (v[i].x + v[i].y) + (v[i].z + v[i].w);
    }
#pragma unroll
    for (int o = 16; o; o >>= 1) sum += __shfl_xor_sync(0xffffffffu, sum, o);
    float inv = 1.0f / sum;
#pragma unroll
    for (int i = 0; i < 16; i++) {
        if (i > rt) continue;
        float a0 = v[i].x*inv, a1 = v[i].y*inv, a2 = v[i].z*inv, a3 = v[i].w*inv;
        __nv_bfloat16 h0=__float2bfloat16(a0), h1=__float2bfloat16(a1),
                      h2=__float2bfloat16(a2), h3=__float2bfloat16(a3);
        __nv_bfloat16 l0=__float2bfloat16(a0-__bfloat162float(h0)),
                      l1=__float2bfloat16(a1-__bfloat162float(h1)),
                      l2=__float2bfloat16(a2-__bfloat162float(h2)),
                      l3=__float2bfloat16(a3-__bfloat162float(h3));
        ph[lane + i*32] = make_uint2(
            (uint32_t)__bfloat16_as_ushort(h0)|((uint32_t)__bfloat16_as_ushort(h1)<<16),
            (uint32_t)__bfloat16_as_ushort(h2)|((uint32_t)__bfloat16_as_ushort(h3)<<16));
        pl[lane + i*32] = make_uint2(
            (uint32_t)__bfloat16_as_ushort(l0)|((uint32_t)__bfloat16_as_ushort(l1)<<16),
            (uint32_t)__bfloat16_as_ushort(l2)|((uint32_t)__bfloat16_as_ushort(l3)<<16));
    }
}

// PV: bf16x3 NN gemm; fp16-split output for the 2-term out gemm. Heavy-first y.
__global__ void __launch_bounds__(256, 2) k_pv_mma(void)
{
    int bh = blockIdx.z, b = bh >> 3, h = bh & 7;
    int m0 = (15 - blockIdx.y) * 128;     // heavy tiles (large K) first
    int n0 = blockIdx.x * 128;
    const __nv_bfloat16* Ah = g_ph + (size_t)bh * SS * SS;
    const __nv_bfloat16* Al = g_pl + (size_t)bh * SS * SS;
    const __nv_bfloat16* Bh = g_vh + (size_t)bh * SS * DK;
    const __nv_bfloat16* Bl = g_vl + (size_t)bh * SS * DK;
    size_t base = (size_t)b * SS * 4096 + h * 512 + n0;
    gemm_mma<3, false, 3>(Ah, Al, SS, Bh, Bl, 512, m0 + 128, m0, n0, 1.f,
                          nullptr, 0, g_hoh + base, g_hol + base, 4096);
}

// out GEMM: fp16x2 (2 MMAs/k16), k-split into 4 slices.
__global__ void __launch_bounds__(256, 2) k_out_mma(void)
{
    int m0 = blockIdx.y * 128, n0 = blockIdx.x * 128, sl = blockIdx.z;
    int koff = sl * 1024;
    gemm_mma<1, true, 2>(g_hoh + koff, g_hol + koff, 4096,
                         g_wuh + koff, g_wul + koff, 4096,
                         1024, m0, n0, 1.f,
                         g_op[sl], 512, nullptr, nullptr, 0);
}

__global__ void __launch_bounds__(256) k_reduce_out(float* __restrict__ out)
{
    int i = blockIdx.x * blockDim.x + threadIdx.x;
    float4 a = reinterpret_cast<const float4*>(g_op[0])[i];
    float4 b = reinterpret_cast<const float4*>(g_op[1])[i];
    float4 c = reinterpret_cast<const float4*>(g_op[2])[i];
    float4 d = reinterpret_cast<const float4*>(g_op[3])[i];
    float4 o;
    o.x = (a.x + b.x) + (c.x + d.x);
    o.y = (a.y + b.y) + (c.y + d.y);
    o.z = (a.z + b.z) + (c.z + d.z);
    o.w = (a.w + b.w) + (c.w + d.w);
    reinterpret_cast<float4*>(out)[i] = o;
}

// ---------------------------------------------------------------------------
extern "C" void kernel_launch(void* const* d_in, const int* in_sizes, int n_in,
                              void* d_out, int out_size)
{
    const float* x  = (const float*)d_in[0];
    const float* Wq = (const float*)d_in[1];
    const float* Wk = (const float*)d_in[2];
    const float* Wv = (const float*)d_in[3];
    const float* Wu = (const float*)d_in[4];
    float* out = (float*)d_out;

    cudaFuncSetAttribute(k_qkv_mma,    cudaFuncAttributeMaxDynamicSharedMemorySize, SMEM_DYN);
    cudaFuncSetAttribute(k_scores_mma, cudaFuncAttributeMaxDynamicSharedMemorySize, SMEM_DYN);
    cudaFuncSetAttribute(k_pv_mma,     cudaFuncAttributeMaxDynamicSharedMemorySize, SMEM_DYN);
    cudaFuncSetAttribute(k_out_mma,    cudaFuncAttributeMaxDynamicSharedMemorySize, SMEM_DYN);

    const int n4 = TT * DK / 4;
    k_dummy     <<<1, 32>>>();                             // launch 1
    k_split_all <<<dim3(n4 / 256, 5), 256>>>(x, Wq, Wk, Wv, Wu);  // 2
    k_qkv_mma   <<<dim3(32, 32, 3),  256, SMEM_DYN>>>();   // 3
    k_scores_mma<<<dim3(136, 1, NH), 256, SMEM_DYN>>>();   // 4  <- ncu slot
    k_softmax   <<<NH * SS / 8, 256>>>();
    k_pv_mma    <<<dim3(4, 16, NH),  256, SMEM_DYN>>>();
    k_out_mma   <<<dim3(4, 32, 4),   256, SMEM_DYN>>>();
    k_reduce_out<<<(TT * 512 / 4) / 256, 256>>>(out);
}

// round 13
// speedup vs baseline: 2.3209x; 1.3596x over previous
#include <cuda_runtime.h>
#include <cuda_fp16.h>
#include <math_constants.h>
#include <cstdint>

#define BB 2
#define SS 2048
#define HH 8
#define DK 512
#define TT (BB*SS)      // 4096 tokens
#define NH (BB*HH)      // 16 (b,h) pairs

// ---------------- static device scratch (no allocs allowed) ----------------
__device__ __half g_x1[TT*512],  g_x2[TT*512];          // x: 2 fp16 digits
__device__ __half g_wq1[4096*512];                      // W: hi digit only (B-side)
__device__ __half g_wk1[4096*512];
__device__ __half g_wv1[4096*512];
__device__ __half g_wu1[512*4096];
__device__ __half g_q1[NH*SS*DK], g_q2[NH*SS*DK];       // q: 2 digits (A-side)
__device__ __half g_k1[NH*SS*DK];                       // k: hi only (B-side)
__device__ __half g_v1[NH*SS*DK];                       // v: hi only (B-side, natural [t][e])
__device__ float  g_s [(size_t)NH*SS*SS];               // fp32 scores (lower tri)
__device__ __half g_p1[(size_t)NH*SS*SS], g_p2[(size_t)NH*SS*SS];
__device__ __half g_ho1[(size_t)TT*4096], g_ho2[(size_t)TT*4096];
__device__ float  g_op[4][(size_t)TT*512];              // out k-split partials

// ---------------- helpers ----------------
__device__ __forceinline__ uint32_t smem_u32(const void* p){
    uint32_t a; asm("{ .reg .u64 t; cvta.to.shared.u64 t, %1; cvt.u32.u64 %0, t; }":"=r"(a):"l"(p)); return a;
}
__device__ __forceinline__ void ldsm4(uint32_t* r, uint32_t addr){
    asm volatile("ldmatrix.sync.aligned.m8n8.x4.shared.b16 {%0,%1,%2,%3}, [%4];"
        : "=r"(r[0]),"=r"(r[1]),"=r"(r[2]),"=r"(r[3]) : "r"(addr));
}
__device__ __forceinline__ void ldsm4t(uint32_t* r, uint32_t addr){
    asm volatile("ldmatrix.sync.aligned.m8n8.x4.trans.shared.b16 {%0,%1,%2,%3}, [%4];"
        : "=r"(r[0]),"=r"(r[1]),"=r"(r[2]),"=r"(r[3]) : "r"(addr));
}
__device__ __forceinline__ void mma_f16(float* c, const uint32_t* a, uint32_t b0, uint32_t b1){
    asm volatile("mma.sync.aligned.m16n8k16.row.col.f32.f16.f16.f32 "
        "{%0,%1,%2,%3}, {%4,%5,%6,%7}, {%8,%9}, {%0,%1,%2,%3};"
        : "+f"(c[0]),"+f"(c[1]),"+f"(c[2]),"+f"(c[3])
        : "r"(a[0]),"r"(a[1]),"r"(a[2]),"r"(a[3]), "r"(b0),"r"(b1));
}
__device__ __forceinline__ void cp16(uint32_t dst, const void* src){
    asm volatile("cp.async.cg.shared.global [%0], [%1], 16;" :: "r"(dst), "l"(src) : "memory");
}
#define CP_COMMIT() asm volatile("cp.async.commit_group;" ::: "memory")
template<int N> __device__ __forceinline__ void cp_wait(){
    asm volatile("cp.async.wait_group %0;" :: "n"(N) : "memory");
}
__device__ __forceinline__ uint32_t swzA(uint32_t row, uint32_t ch){
    return row * 64 + ((ch ^ ((row >> 1) & 3)) << 4);
}
__device__ __forceinline__ uint32_t swzB(uint32_t row, uint32_t ch){
    return row * 256 + ((ch ^ (row & 7)) << 4);
}

#define STAGE 24576u        // A1 8K | A2 8K | B 8K
#define NSTAGE 3
#define SMEM_DYN (STAGE*NSTAGE)   // 73728 -> 2 CTAs/SM

// ---------------------------------------------------------------------------
// fp16x2 warp-MMA GEMM: D = scale * (A1 + A2) . op(B1), fp32 accumulate.
// 3-stage cp.async, BK=32, block 128x128, 8 warps (4Mx2N), warp tile 32x64.
// BT=true: B[N,K] (NT).  BT=false: B[K,N] (NN, trans-ldsm).
// EPI: 0 fp32+causal-mask | 1 fp32 | 3 split-fp16 (O1,O2) | 4 fp16 hi-only (O1)
// ---------------------------------------------------------------------------
template<int EPI, bool BT>
__device__ void gemm_mma(
    const __half* __restrict__ A1, const __half* __restrict__ A2, int lda,
    const __half* __restrict__ B1, int ldb,
    int kCount, int m0, int n0, float scale,
    float* __restrict__ Cf, int ldc,
    __half* __restrict__ O1, __half* __restrict__ O2, int orow)
{
    extern __shared__ char sm[];
    const int tid = threadIdx.x, lane = tid & 31, wid = tid >> 5;
    const int wm = wid & 3, wn = wid >> 2;
    const int g = lane >> 2, t4 = lane & 3;
    const uint32_t sbase = smem_u32(sm);

    const int mtx = lane >> 3, ri = lane & 7;
    const int lrow = ((mtx & 1) << 3) + ri;
    const int lkh  = mtx >> 1;
    const int brow = ((lane >> 4) << 3) + ri;
    const int bchh = (lane >> 3) & 1;

    float acc[64];
#pragma unroll
    for (int i = 0; i < 64; i++) acc[i] = 0.f;

    const int nk = kCount >> 5;

    auto load_chunk = [&](int kc){
        const uint32_t sb = sbase + (uint32_t)(kc % NSTAGE) * STAGE;
        const int k0 = kc << 5;
#pragma unroll
        for (int i = 0; i < 2; i++) {          // A1
            int lin = tid + i * 256;
            int r = lin >> 2, ch = lin & 3;
            cp16(sb + swzA(r, ch), A1 + (size_t)(m0 + r) * lda + k0 + ch * 8);
        }
#pragma unroll
        for (int i = 0; i < 2; i++) {          // A2
            int lin = tid + i * 256;
            int r = lin >> 2, ch = lin & 3;
            cp16(sb + 8192 + swzA(r, ch), A2 + (size_t)(m0 + r) * lda + k0 + ch * 8);
        }
        if (BT) {
#pragma unroll
            for (int i = 0; i < 2; i++) {      // B[N,K]
                int lin = tid + i * 256;
                int r = lin >> 2, ch = lin & 3;
                cp16(sb + 16384 + swzA(r, ch), B1 + (size_t)(n0 + r) * ldb + k0 + ch * 8);
            }
        } else {
#pragma unroll
            for (int i = 0; i < 2; i++) {      // B[K,N]: 32 rows x 256B
                int lin = tid + i * 256;
                int r = lin >> 4, ch = lin & 15;
                cp16(sb + 16384 + swzB(r, ch), B1 + (size_t)(k0 + r) * ldb + n0 + ch * 8);
            }
        }
    };

    load_chunk(0);            CP_COMMIT();
    if (nk > 1) load_chunk(1);
    CP_COMMIT();

    for (int kc = 0; kc < nk; kc++) {
        if (kc + 2 < nk) load_chunk(kc + 2);
        CP_COMMIT();
        cp_wait<2>();
        __syncthreads();

        const uint32_t cb = sbase + (uint32_t)(kc % NSTAGE) * STAGE;
#pragma unroll
        for (int kk = 0; kk < 2; kk++) {
            const int ch = kk * 2 + lkh;
            uint32_t aH[8], aL[8];
#pragma unroll
            for (int s = 0; s < 2; s++) {
                uint32_t off = swzA((uint32_t)(wm * 32 + s * 16 + lrow), ch);
                ldsm4(aH + s * 4, cb + off);
                ldsm4(aL + s * 4, cb + 8192 + off);
            }
#pragma unroll
            for (int nbp = 0; nbp < 2; nbp++) {
                uint32_t bh[8];
#pragma unroll
                for (int q = 0; q < 2; q++) {
                    int nb = nbp * 2 + q;
                    if (BT) {
                        uint32_t off = swzA((uint32_t)(wn * 64 + nb * 16 + lrow), ch);
                        ldsm4(bh + q * 4, cb + 16384 + off);
                    } else {
                        uint32_t off = swzB((uint32_t)(kk * 16 + brow),
                                            (uint32_t)(wn * 8 + nb * 2 + bchh));
                        ldsm4t(bh + q * 4, cb + 16384 + off);
                    }
                }
#pragma unroll
                for (int t = 0; t < 2; t++) {
#pragma unroll
                    for (int q = 0; q < 2; q++) {
#pragma unroll
                        for (int mi = 0; mi < 2; mi++) {
#pragma unroll
                            for (int sub = 0; sub < 2; sub++) {
                                int nb = nbp * 2 + q;
                                float* c = acc + (mi * 8 + nb * 2 + sub) * 4;
                                const uint32_t* a = t ? (aL + mi * 4) : (aH + mi * 4);
                                mma_f16(c, a, bh[q * 4 + sub], bh[q * 4 + sub + 2]);
                            }
                        }
                    }
                }
            }
        }
        __syncthreads();
    }

    // ---- epilogue
#pragma unroll
    for (int mi = 0; mi < 2; mi++) {
#pragma unroll
        for (int nbi = 0; nbi < 8; nbi++) {
            const float* c = acc + (mi * 8 + nbi) * 4;
            int rl = wm * 32 + mi * 16 + g;
            int cl = wn * 64 + nbi * 8 + 2 * t4;
            if (EPI <= 1) {
                int gr0 = m0 + rl, gc = n0 + cl;
                float v0 = c[0] * scale, v1 = c[1] * scale;
                float v2 = c[2] * scale, v3 = c[3] * scale;
                if (EPI == 0) {
                    if (gc     > gr0)     v0 = -CUDART_INF_F;
                    if (gc + 1 > gr0)     v1 = -CUDART_INF_F;
                    if (gc     > gr0 + 8) v2 = -CUDART_INF_F;
                    if (gc + 1 > gr0 + 8) v3 = -CUDART_INF_F;
                }
                *reinterpret_cast<float2*>(Cf + (size_t)gr0 * ldc + gc)       = make_float2(v0, v1);
                *reinterpret_cast<float2*>(Cf + (size_t)(gr0 + 8) * ldc + gc) = make_float2(v2, v3);
            } else {
                __half h0 = __float2half(c[0]);
                __half h1 = __float2half(c[1]);
                __half h2 = __float2half(c[2]);
                __half h3 = __float2half(c[3]);
                size_t gm = (size_t)(m0 + rl);
                size_t o0 = gm * orow + cl, o1 = o0 + (size_t)8 * orow;
                *reinterpret_cast<__half2*>(O1 + o0) = __half2(h0, h1);
                *reinterpret_cast<__half2*>(O1 + o1) = __half2(h2, h3);
                if (EPI == 3) {
                    __half l0 = __float2half(c[0] - __half2float(h0));
                    __half l1 = __float2half(c[1] - __half2float(h1));
                    __half l2 = __float2half(c[2] - __half2float(h2));
                    __half l3 = __float2half(c[3] - __half2float(h3));
                    *reinterpret_cast<__half2*>(O2 + o0) = __half2(l0, l1);
                    *reinterpret_cast<__half2*>(O2 + o1) = __half2(l2, l3);
                }
            }
        }
    }
}

// ---------------------------------------------------------------------------
__global__ void k_dummy(void) {}   // keeps scores in the ncu capture slot

// z=0: x -> 2 digits; z=1..4: W -> hi digit only
__global__ void __launch_bounds__(256) k_split_all(
    const float* __restrict__ x,  const float* __restrict__ Wq,
    const float* __restrict__ Wk, const float* __restrict__ Wv,
    const float* __restrict__ Wu)
{
    const int z = blockIdx.y;
    const float* s;
    __half *h, *l = nullptr;
    switch (z) {
        case 0: s = x;  h = g_x1;  l = g_x2; break;
        case 1: s = Wq; h = g_wq1; break;
        case 2: s = Wk; h = g_wk1; break;
        case 3: s = Wv; h = g_wv1; break;
        default: s = Wu; h = g_wu1; break;
    }
    int i = blockIdx.x * blockDim.x + threadIdx.x;
    float4 v = reinterpret_cast<const float4*>(s)[i];
    __half h0=__float2half(v.x), h1=__float2half(v.y),
           h2=__float2half(v.z), h3=__float2half(v.w);
    uint2 hv = make_uint2((uint32_t)__half_as_ushort(h0)|((uint32_t)__half_as_ushort(h1)<<16),
                          (uint32_t)__half_as_ushort(h2)|((uint32_t)__half_as_ushort(h3)<<16));
    reinterpret_cast<uint2*>(h)[i] = hv;
    if (z == 0) {
        __half l0=__float2half(v.x-__half2float(h0)),
               l1=__float2half(v.y-__half2float(h1)),
               l2=__float2half(v.z-__half2float(h2)),
               l3=__float2half(v.w-__half2float(h3));
        uint2 lv = make_uint2((uint32_t)__half_as_ushort(l0)|((uint32_t)__half_as_ushort(l1)<<16),
                              (uint32_t)__half_as_ushort(l2)|((uint32_t)__half_as_ushort(l3)<<16));
        reinterpret_cast<uint2*>(l)[i] = lv;
    }
}

// QKV: z=0 q (2-digit out), z=1 k (hi only), z=2 v (hi only)
__global__ void __launch_bounds__(256, 2) k_qkv_mma(void)
{
    int n0 = blockIdx.x * 128, m0 = blockIdx.y * 128, z = blockIdx.z;
    int b = m0 >> 11, h = n0 >> 9, e0 = n0 & 511;
    size_t base = ((size_t)(b * HH + h) * SS) * DK + e0 - (size_t)(b * SS) * DK;
    if (z == 0)
        gemm_mma<3, true>(g_x1, g_x2, 512, g_wq1, 512, 512, m0, n0, 1.f,
                          nullptr, 0, g_q1 + base, g_q2 + base, 512);
    else if (z == 1)
        gemm_mma<4, true>(g_x1, g_x2, 512, g_wk1, 512, 512, m0, n0, 1.f,
                          nullptr, 0, g_k1 + base, nullptr, 512);
    else
        gemm_mma<4, true>(g_x1, g_x2, 512, g_wv1, 512, 512, m0, n0, 1.f,
                          nullptr, 0, g_v1 + base, nullptr, 512);
}

// Triangular grid over lower-tri tiles.
__global__ void __launch_bounds__(256, 2) k_scores_mma(void)
{
    int t = blockIdx.x, bh = blockIdx.z;
    int r = (int)((sqrtf(8.f * t + 1.f) - 1.f) * 0.5f);
    while ((r + 1) * (r + 2) / 2 <= t) r++;
    while (r * (r + 1) / 2 > t) r--;
    int c = t - r * (r + 1) / 2;
    int m0 = r * 128, n0 = c * 128;
    float* Cf = g_s + (size_t)bh * SS * SS;
    size_t ob = (size_t)bh * SS * DK;
    gemm_mma<0, true>(g_q1 + ob, g_q2 + ob, 512, g_k1 + ob, 512,
                      512, m0, n0, 0.04419417382415922f, Cf, SS, nullptr, nullptr, 0);
}

__global__ void __launch_bounds__(256) k_softmax(void)
{
    int row  = blockIdx.x * 8 + (threadIdx.x >> 5);
    int lane = threadIdx.x & 31;
    int r    = row & (SS - 1);
    int rt   = r >> 7;
    const float4* p = reinterpret_cast<const float4*>(g_s + (size_t)row * SS);
    uint2* p1 = reinterpret_cast<uint2*>(g_p1 + (size_t)row * SS);
    uint2* p2 = reinterpret_cast<uint2*>(g_p2 + (size_t)row * SS);

    float4 v[16];
    float mx = -CUDART_INF_F;
#pragma unroll
    for (int i = 0; i < 16; i++) {
        if (i <= rt) {
            v[i] = p[lane + i * 32];
            mx = fmaxf(mx, fmaxf(fmaxf(v[i].x, v[i].y), fmaxf(v[i].z, v[i].w)));
        }
    }
#pragma unroll
    for (int o = 16; o; o >>= 1) mx = fmaxf(mx, __shfl_xor_sync(0xffffffffu, mx, o));
    float sum = 0.0f;
#pragma unroll
    for (int i = 0; i < 16; i++) {
        if (i > rt) continue;
        v[i].x = __expf(v[i].x - mx); v[i].y = __expf(v[i].y - mx);
        v[i].z = __expf(v[i].z - mx); v[i].w = __expf(v[i].w - mx);
        sum += (v[i].x + v[i].y) + (v[i].z + v[i].w);
    }
#pragma unroll
    for (int o = 16; o; o >>= 1) sum += __shfl_xor_sync(0xffffffffu, sum, o);
    float inv = 1.0f / sum;
#pragma unroll
    for (int i = 0; i < 16; i++) {
        if (i > rt) continue;
        float a0 = v[i].x*inv, a1 = v[i].y*inv, a2 = v[i].z*inv, a3 = v[i].w*inv;
        __half h0=__float2half(a0), h1=__float2half(a1),
               h2=__float2half(a2), h3=__float2half(a3);
        __half l0=__float2half(a0-__half2float(h0)),
               l1=__float2half(a1-__half2float(h1)),
               l2=__float2half(a2-__half2float(h2)),
               l3=__float2half(a3-__half2float(h3));
        p1[lane + i*32] = make_uint2(
            (uint32_t)__half_as_ushort(h0)|((uint32_t)__half_as_ushort(h1)<<16),
            (uint32_t)__half_as_ushort(h2)|((uint32_t)__half_as_ushort(h3)<<16));
        p2[lane + i*32] = make_uint2(
            (uint32_t)__half_as_ushort(l0)|((uint32_t)__half_as_ushort(l1)<<16),
            (uint32_t)__half_as_ushort(l2)|((uint32_t)__half_as_ushort(l3)<<16));
    }
}

// PV: NN gemm, probs (2-digit) x V (hi only). Heavy-first m tiles.
__global__ void __launch_bounds__(256, 2) k_pv_mma(void)
{
    int bh = blockIdx.z, b = bh >> 3, h = bh & 7;
    int m0 = (15 - blockIdx.y) * 128;
    int n0 = blockIdx.x * 128;
    const __half* A1 = g_p1 + (size_t)bh * SS * SS;
    const __half* A2 = g_p2 + (size_t)bh * SS * SS;
    const __half* B1 = g_v1 + (size_t)bh * SS * DK;
    size_t base = (size_t)b * SS * 4096 + h * 512 + n0;
    gemm_mma<3, false>(A1, A2, SS, B1, 512, m0 + 128, m0, n0, 1.f,
                       nullptr, 0, g_ho1 + base, g_ho2 + base, 4096);
}

// out GEMM: fp16x2, k-split into 4 slices.
__global__ void __launch_bounds__(256, 2) k_out_mma(void)
{
    int m0 = blockIdx.y * 128, n0 = blockIdx.x * 128, sl = blockIdx.z;
    int koff = sl * 1024;
    gemm_mma<1, true>(g_ho1 + koff, g_ho2 + koff, 4096,
                      g_wu1 + koff, 4096,
                      1024, m0, n0, 1.f,
                      g_op[sl], 512, nullptr, nullptr, 0);
}

__global__ void __launch_bounds__(256) k_reduce_out(float* __restrict__ out)
{
    int i = blockIdx.x * blockDim.x + threadIdx.x;
    float4 a = reinterpret_cast<const float4*>(g_op[0])[i];
    float4 b = reinterpret_cast<const float4*>(g_op[1])[i];
    float4 c = reinterpret_cast<const float4*>(g_op[2])[i];
    float4 d = reinterpret_cast<const float4*>(g_op[3])[i];
    float4 o;
    o.x = (a.x + b.x) + (c.x + d.x);
    o.y = (a.y + b.y) + (c.y + d.y);
    o.z = (a.z + b.z) + (c.z + d.z);
    o.w = (a.w + b.w) + (c.w + d.w);
    reinterpret_cast<float4*>(out)[i] = o;
}

// ---------------------------------------------------------------------------
extern "C" void kernel_launch(void* const* d_in, const int* in_sizes, int n_in,
                              void* d_out, int out_size)
{
    const float* x  = (const float*)d_in[0];
    const float* Wq = (const float*)d_in[1];
    const float* Wk = (const float*)d_in[2];
    const float* Wv = (const float*)d_in[3];
    const float* Wu = (const float*)d_in[4];
    float* out = (float*)d_out;

    cudaFuncSetAttribute(k_qkv_mma,    cudaFuncAttributeMaxDynamicSharedMemorySize, SMEM_DYN);
    cudaFuncSetAttribute(k_scores_mma, cudaFuncAttributeMaxDynamicSharedMemorySize, SMEM_DYN);
    cudaFuncSetAttribute(k_pv_mma,     cudaFuncAttributeMaxDynamicSharedMemorySize, SMEM_DYN);
    cudaFuncSetAttribute(k_out_mma,    cudaFuncAttributeMaxDynamicSharedMemorySize, SMEM_DYN);

    const int n4 = TT * DK / 4;
    k_dummy     <<<1, 32>>>();                                    // 1
    k_split_all <<<dim3(n4 / 256, 5), 256>>>(x, Wq, Wk, Wv, Wu);  // 2
    k_qkv_mma   <<<dim3(32, 32, 3),  256, SMEM_DYN>>>();          // 3
    k_scores_mma<<<dim3(136, 1, NH), 256, SMEM_DYN>>>();          // 4 <- ncu slot
    k_softmax   <<<NH * SS / 8, 256>>>();
    k_pv_mma    <<<dim3(4, 16, NH),  256, SMEM_DYN>>>();
    k_out_mma   <<<dim3(4, 32, 4),   256, SMEM_DYN>>>();
    k_reduce_out<<<(TT * 512 / 4) / 256, 256>>>(out);
}

// round 14
// speedup vs baseline: 2.9610x; 1.2758x over previous
#include <cuda_runtime.h>
#include <cuda_fp16.h>
#include <math_constants.h>
#include <cstdint>

#define BB 2
#define SS 2048
#define HH 8
#define DK 512
#define TT (BB*SS)      // 4096 tokens
#define NH (BB*HH)      // 16 (b,h) pairs

// ---------------- static device scratch (no allocs allowed) ----------------
__device__ __half g_x1[TT*512],  g_x2[TT*512];          // x: 2 fp16 digits
__device__ __half g_wq1[4096*512];                      // W: hi digit only
__device__ __half g_wk1[4096*512];
__device__ __half g_wv1[4096*512];
__device__ __half g_wu1[512*4096];
__device__ __half g_q1[NH*SS*DK];                       // q: hi only (scores 1-term)
__device__ __half g_k1[NH*SS*DK];                       // k: hi only
__device__ __half g_v1[NH*SS*DK];                       // v: hi only, natural [t][e]
__device__ float  g_s [(size_t)NH*SS*SS];               // fp32 scores (lower tri)
__device__ __half g_p1[(size_t)NH*SS*SS];               // probs: hi only (pv 1-term)
__device__ __half g_ho1[(size_t)TT*4096], g_ho2[(size_t)TT*4096];  // heads_out 2-digit
__device__ float  g_op[4][(size_t)TT*512];              // out k-split partials

// ---------------- helpers ----------------
__device__ __forceinline__ uint32_t smem_u32(const void* p){
    uint32_t a; asm("{ .reg .u64 t; cvta.to.shared.u64 t, %1; cvt.u32.u64 %0, t; }":"=r"(a):"l"(p)); return a;
}
__device__ __forceinline__ void ldsm4(uint32_t* r, uint32_t addr){
    asm volatile("ldmatrix.sync.aligned.m8n8.x4.shared.b16 {%0,%1,%2,%3}, [%4];"
        : "=r"(r[0]),"=r"(r[1]),"=r"(r[2]),"=r"(r[3]) : "r"(addr));
}
__device__ __forceinline__ void ldsm4t(uint32_t* r, uint32_t addr){
    asm volatile("ldmatrix.sync.aligned.m8n8.x4.trans.shared.b16 {%0,%1,%2,%3}, [%4];"
        : "=r"(r[0]),"=r"(r[1]),"=r"(r[2]),"=r"(r[3]) : "r"(addr));
}
__device__ __forceinline__ void mma_f16(float* c, const uint32_t* a, uint32_t b0, uint32_t b1){
    asm volatile("mma.sync.aligned.m16n8k16.row.col.f32.f16.f16.f32 "
        "{%0,%1,%2,%3}, {%4,%5,%6,%7}, {%8,%9}, {%0,%1,%2,%3};"
        : "+f"(c[0]),"+f"(c[1]),"+f"(c[2]),"+f"(c[3])
        : "r"(a[0]),"r"(a[1]),"r"(a[2]),"r"(a[3]), "r"(b0),"r"(b1));
}
__device__ __forceinline__ void cp16(uint32_t dst, const void* src){
    asm volatile("cp.async.cg.shared.global [%0], [%1], 16;" :: "r"(dst), "l"(src) : "memory");
}
#define CP_COMMIT() asm volatile("cp.async.commit_group;" ::: "memory")
template<int N> __device__ __forceinline__ void cp_wait(){
    asm volatile("cp.async.wait_group %0;" :: "n"(N) : "memory");
}
__device__ __forceinline__ uint32_t swzA(uint32_t row, uint32_t ch){
    return row * 64 + ((ch ^ ((row >> 1) & 3)) << 4);
}
__device__ __forceinline__ uint32_t swzB(uint32_t row, uint32_t ch){
    return row * 256 + ((ch ^ (row & 7)) << 4);
}

#define STAGE 24576u        // A1 8K | A2 8K (unused if TERMS==1) | B 8K
#define NSTAGE 3
#define SMEM_DYN (STAGE*NSTAGE)   // 73728 -> 2 CTAs/SM

// ---------------------------------------------------------------------------
// fp16 warp-MMA GEMM: D = scale * (A1 [+ A2]) . op(B1), fp32 accumulate.
// TERMS = 1 or 2 (number of A digits). 3-stage cp.async, BK=32,
// block 128x128, 8 warps (4Mx2N), warp tile 32x64.
// BT=true: B[N,K] (NT).  BT=false: B[K,N] (NN, trans-ldsm).
// EPI: 0 fp32+causal-mask | 1 fp32 | 3 split-fp16 (O1,O2) | 4 fp16 hi-only
// ---------------------------------------------------------------------------
template<int EPI, bool BT, int TERMS>
__device__ void gemm_mma(
    const __half* __restrict__ A1, const __half* __restrict__ A2, int lda,
    const __half* __restrict__ B1, int ldb,
    int kCount, int m0, int n0, float scale,
    float* __restrict__ Cf, int ldc,
    __half* __restrict__ O1, __half* __restrict__ O2, int orow)
{
    extern __shared__ char sm[];
    const int tid = threadIdx.x, lane = tid & 31, wid = tid >> 5;
    const int wm = wid & 3, wn = wid >> 2;
    const int g = lane >> 2, t4 = lane & 3;
    const uint32_t sbase = smem_u32(sm);

    const int mtx = lane >> 3, ri = lane & 7;
    const int lrow = ((mtx & 1) << 3) + ri;
    const int lkh  = mtx >> 1;
    const int brow = ((lane >> 4) << 3) + ri;
    const int bchh = (lane >> 3) & 1;

    float acc[64];
#pragma unroll
    for (int i = 0; i < 64; i++) acc[i] = 0.f;

    const int nk = kCount >> 5;

    auto load_chunk = [&](int kc){
        const uint32_t sb = sbase + (uint32_t)(kc % NSTAGE) * STAGE;
        const int k0 = kc << 5;
#pragma unroll
        for (int i = 0; i < 2; i++) {          // A1
            int lin = tid + i * 256;
            int r = lin >> 2, ch = lin & 3;
            cp16(sb + swzA(r, ch), A1 + (size_t)(m0 + r) * lda + k0 + ch * 8);
        }
        if (TERMS == 2) {
#pragma unroll
            for (int i = 0; i < 2; i++) {      // A2
                int lin = tid + i * 256;
                int r = lin >> 2, ch = lin & 3;
                cp16(sb + 8192 + swzA(r, ch), A2 + (size_t)(m0 + r) * lda + k0 + ch * 8);
            }
        }
        if (BT) {
#pragma unroll
            for (int i = 0; i < 2; i++) {      // B[N,K]
                int lin = tid + i * 256;
                int r = lin >> 2, ch = lin & 3;
                cp16(sb + 16384 + swzA(r, ch), B1 + (size_t)(n0 + r) * ldb + k0 + ch * 8);
            }
        } else {
#pragma unroll
            for (int i = 0; i < 2; i++) {      // B[K,N]: 32 rows x 256B
                int lin = tid + i * 256;
                int r = lin >> 4, ch = lin & 15;
                cp16(sb + 16384 + swzB(r, ch), B1 + (size_t)(k0 + r) * ldb + n0 + ch * 8);
            }
        }
    };

    load_chunk(0);            CP_COMMIT();
    if (nk > 1) load_chunk(1);
    CP_COMMIT();

    for (int kc = 0; kc < nk; kc++) {
        if (kc + 2 < nk) load_chunk(kc + 2);
        CP_COMMIT();
        cp_wait<2>();
        __syncthreads();

        const uint32_t cb = sbase + (uint32_t)(kc % NSTAGE) * STAGE;
#pragma unroll
        for (int kk = 0; kk < 2; kk++) {
            const int ch = kk * 2 + lkh;
            uint32_t aH[8], aL[8];
#pragma unroll
            for (int s = 0; s < 2; s++) {
                uint32_t off = swzA((uint32_t)(wm * 32 + s * 16 + lrow), ch);
                ldsm4(aH + s * 4, cb + off);
                if (TERMS == 2) ldsm4(aL + s * 4, cb + 8192 + off);
            }
#pragma unroll
            for (int nbp = 0; nbp < 2; nbp++) {
                uint32_t bh[8];
#pragma unroll
                for (int q = 0; q < 2; q++) {
                    int nb = nbp * 2 + q;
                    if (BT) {
                        uint32_t off = swzA((uint32_t)(wn * 64 + nb * 16 + lrow), ch);
                        ldsm4(bh + q * 4, cb + 16384 + off);
                    } else {
                        uint32_t off = swzB((uint32_t)(kk * 16 + brow),
                                            (uint32_t)(wn * 8 + nb * 2 + bchh));
                        ldsm4t(bh + q * 4, cb + 16384 + off);
                    }
                }
#pragma unroll
                for (int t = 0; t < TERMS; t++) {
#pragma unroll
                    for (int q = 0; q < 2; q++) {
#pragma unroll
                        for (int mi = 0; mi < 2; mi++) {
#pragma unroll
                            for (int sub = 0; sub < 2; sub++) {
                                int nb = nbp * 2 + q;
                                float* c = acc + (mi * 8 + nb * 2 + sub) * 4;
                                const uint32_t* a = t ? (aL + mi * 4) : (aH + mi * 4);
                                mma_f16(c, a, bh[q * 4 + sub], bh[q * 4 + sub + 2]);
                            }
                        }
                    }
                }
            }
        }
        __syncthreads();
    }

    // ---- epilogue
#pragma unroll
    for (int mi = 0; mi < 2; mi++) {
#pragma unroll
        for (int nbi = 0; nbi < 8; nbi++) {
            const float* c = acc + (mi * 8 + nbi) * 4;
            int rl = wm * 32 + mi * 16 + g;
            int cl = wn * 64 + nbi * 8 + 2 * t4;
            if (EPI <= 1) {
                int gr0 = m0 + rl, gc = n0 + cl;
                float v0 = c[0] * scale, v1 = c[1] * scale;
                float v2 = c[2] * scale, v3 = c[3] * scale;
                if (EPI == 0) {
                    if (gc     > gr0)     v0 = -CUDART_INF_F;
                    if (gc + 1 > gr0)     v1 = -CUDART_INF_F;
                    if (gc     > gr0 + 8) v2 = -CUDART_INF_F;
                    if (gc + 1 > gr0 + 8) v3 = -CUDART_INF_F;
                }
                *reinterpret_cast<float2*>(Cf + (size_t)gr0 * ldc + gc)       = make_float2(v0, v1);
                *reinterpret_cast<float2*>(Cf + (size_t)(gr0 + 8) * ldc + gc) = make_float2(v2, v3);
            } else {
                __half h0 = __float2half(c[0]);
                __half h1 = __float2half(c[1]);
                __half h2 = __float2half(c[2]);
                __half h3 = __float2half(c[3]);
                size_t gm = (size_t)(m0 + rl);
                size_t o0 = gm * orow + cl, o1 = o0 + (size_t)8 * orow;
                *reinterpret_cast<__half2*>(O1 + o0) = __half2(h0, h1);
                *reinterpret_cast<__half2*>(O1 + o1) = __half2(h2, h3);
                if (EPI == 3) {
                    __half l0 = __float2half(c[0] - __half2float(h0));
                    __half l1 = __float2half(c[1] - __half2float(h1));
                    __half l2 = __float2half(c[2] - __half2float(h2));
                    __half l3 = __float2half(c[3] - __half2float(h3));
                    *reinterpret_cast<__half2*>(O2 + o0) = __half2(l0, l1);
                    *reinterpret_cast<__half2*>(O2 + o1) = __half2(l2, l3);
                }
            }
        }
    }
}

// ---------------------------------------------------------------------------
__global__ void k_dummy(void) {}   // keeps scores in the ncu capture slot

// z=0: x -> 2 digits; z=1..4: W -> hi digit only
__global__ void __launch_bounds__(256) k_split_all(
    const float* __restrict__ x,  const float* __restrict__ Wq,
    const float* __restrict__ Wk, const float* __restrict__ Wv,
    const float* __restrict__ Wu)
{
    const int z = blockIdx.y;
    const float* s;
    __half *h, *l = nullptr;
    switch (z) {
        case 0: s = x;  h = g_x1;  l = g_x2; break;
        case 1: s = Wq; h = g_wq1; break;
        case 2: s = Wk; h = g_wk1; break;
        case 3: s = Wv; h = g_wv1; break;
        default: s = Wu; h = g_wu1; break;
    }
    int i = blockIdx.x * blockDim.x + threadIdx.x;
    float4 v = reinterpret_cast<const float4*>(s)[i];
    __half h0=__float2half(v.x), h1=__float2half(v.y),
           h2=__float2half(v.z), h3=__float2half(v.w);
    uint2 hv = make_uint2((uint32_t)__half_as_ushort(h0)|((uint32_t)__half_as_ushort(h1)<<16),
                          (uint32_t)__half_as_ushort(h2)|((uint32_t)__half_as_ushort(h3)<<16));
    reinterpret_cast<uint2*>(h)[i] = hv;
    if (z == 0) {
        __half l0=__float2half(v.x-__half2float(h0)),
               l1=__float2half(v.y-__half2float(h1)),
               l2=__float2half(v.z-__half2float(h2)),
               l3=__float2half(v.w-__half2float(h3));
        uint2 lv = make_uint2((uint32_t)__half_as_ushort(l0)|((uint32_t)__half_as_ushort(l1)<<16),
                              (uint32_t)__half_as_ushort(l2)|((uint32_t)__half_as_ushort(l3)<<16));
        reinterpret_cast<uint2*>(l)[i] = lv;
    }
}

// QKV: 2-term (x two digits), hi-only outputs for q, k, v.
__global__ void __launch_bounds__(256, 2) k_qkv_mma(void)
{
    int n0 = blockIdx.x * 128, m0 = blockIdx.y * 128, z = blockIdx.z;
    int b = m0 >> 11, h = n0 >> 9, e0 = n0 & 511;
    size_t base = ((size_t)(b * HH + h) * SS) * DK + e0 - (size_t)(b * SS) * DK;
    const __half* W = (z == 0) ? g_wq1 : (z == 1) ? g_wk1 : g_wv1;
    __half* O      = (z == 0) ? g_q1  : (z == 1) ? g_k1  : g_v1;
    gemm_mma<4, true, 2>(g_x1, g_x2, 512, W, 512, 512, m0, n0, 1.f,
                         nullptr, 0, O + base, nullptr, 512);
}

// Scores: 1-term q1 x k1. Triangular grid over lower-tri tiles.
__global__ void __launch_bounds__(256, 2) k_scores_mma(void)
{
    int t = blockIdx.x, bh = blockIdx.z;
    int r = (int)((sqrtf(8.f * t + 1.f) - 1.f) * 0.5f);
    while ((r + 1) * (r + 2) / 2 <= t) r++;
    while (r * (r + 1) / 2 > t) r--;
    int c = t - r * (r + 1) / 2;
    int m0 = r * 128, n0 = c * 128;
    float* Cf = g_s + (size_t)bh * SS * SS;
    size_t ob = (size_t)bh * SS * DK;
    gemm_mma<0, true, 1>(g_q1 + ob, nullptr, 512, g_k1 + ob, 512,
                         512, m0, n0, 0.04419417382415922f, Cf, SS, nullptr, nullptr, 0);
}

__global__ void __launch_bounds__(256) k_softmax(void)
{
    int row  = blockIdx.x * 8 + (threadIdx.x >> 5);
    int lane = threadIdx.x & 31;
    int r    = row & (SS - 1);
    int rt   = r >> 7;
    const float4* p = reinterpret_cast<const float4*>(g_s + (size_t)row * SS);
    uint2* p1 = reinterpret_cast<uint2*>(g_p1 + (size_t)row * SS);

    float4 v[16];
    float mx = -CUDART_INF_F;
#pragma unroll
    for (int i = 0; i < 16; i++) {
        if (i <= rt) {
            v[i] = p[lane + i * 32];
            mx = fmaxf(mx, fmaxf(fmaxf(v[i].x, v[i].y), fmaxf(v[i].z, v[i].w)));
        }
    }
#pragma unroll
    for (int o = 16; o; o >>= 1) mx = fmaxf(mx, __shfl_xor_sync(0xffffffffu, mx, o));
    float sum = 0.0f;
#pragma unroll
    for (int i = 0; i < 16; i++) {
        if (i > rt) continue;
        v[i].x = __expf(v[i].x - mx); v[i].y = __expf(v[i].y - mx);
        v[i].z = __expf(v[i].z - mx); v[i].w = __expf(v[i].w - mx);
        sum += (v[i].x + v[i].y) + (v[i].z + v[i].w);
    }
#pragma unroll
    for (int o = 16; o; o >>= 1) sum += __shfl_xor_sync(0xffffffffu, sum, o);
    float inv = 1.0f / sum;
#pragma unroll
    for (int i = 0; i < 16; i++) {
        if (i > rt) continue;
        __half h0=__float2half(v[i].x*inv), h1=__float2half(v[i].y*inv),
               h2=__float2half(v[i].z*inv), h3=__float2half(v[i].w*inv);
        p1[lane + i*32] = make_uint2(
            (uint32_t)__half_as_ushort(h0)|((uint32_t)__half_as_ushort(h1)<<16),
            (uint32_t)__half_as_ushort(h2)|((uint32_t)__half_as_ushort(h3)<<16));
    }
}

// PV: 1-term p1 x v1 (NN). Heavy-first m tiles. 2-digit ho output.
__global__ void __launch_bounds__(256, 2) k_pv_mma(void)
{
    int bh = blockIdx.z, b = bh >> 3, h = bh & 7;
    int m0 = (15 - blockIdx.y) * 128;
    int n0 = blockIdx.x * 128;
    const __half* A1 = g_p1 + (size_t)bh * SS * SS;
    const __half* B1 = g_v1 + (size_t)bh * SS * DK;
    size_t base = (size_t)b * SS * 4096 + h * 512 + n0;
    gemm_mma<3, false, 1>(A1, nullptr, SS, B1, 512, m0 + 128, m0, n0, 1.f,
                          nullptr, 0, g_ho1 + base, g_ho2 + base, 4096);
}

// out GEMM: 2-term ho x Wu (hi), k-split into 4 slices.
__global__ void __launch_bounds__(256, 2) k_out_mma(void)
{
    int m0 = blockIdx.y * 128, n0 = blockIdx.x * 128, sl = blockIdx.z;
    int koff = sl * 1024;
    gemm_mma<1, true, 2>(g_ho1 + koff, g_ho2 + koff, 4096,
                         g_wu1 + koff, 4096,
                         1024, m0, n0, 1.f,
                         g_op[sl], 512, nullptr, nullptr, 0);
}

__global__ void __launch_bounds__(256) k_reduce_out(float* __restrict__ out)
{
    int i = blockIdx.x * blockDim.x + threadIdx.x;
    float4 a = reinterpret_cast<const float4*>(g_op[0])[i];
    float4 b = reinterpret_cast<const float4*>(g_op[1])[i];
    float4 c = reinterpret_cast<const float4*>(g_op[2])[i];
    float4 d = reinterpret_cast<const float4*>(g_op[3])[i];
    float4 o;
    o.x = (a.x + b.x) + (c.x + d.x);
    o.y = (a.y + b.y) + (c.y + d.y);
    o.z = (a.z + b.z) + (c.z + d.z);
    o.w = (a.w + b.w) + (c.w + d.w);
    reinterpret_cast<float4*>(out)[i] = o;
}

// ---------------------------------------------------------------------------
extern "C" void kernel_launch(void* const* d_in, const int* in_sizes, int n_in,
                              void* d_out, int out_size)
{
    const float* x  = (const float*)d_in[0];
    const float* Wq = (const float*)d_in[1];
    const float* Wk = (const float*)d_in[2];
    const float* Wv = (const float*)d_in[3];
    const float* Wu = (const float*)d_in[4];
    float* out = (float*)d_out;

    cudaFuncSetAttribute(k_qkv_mma,    cudaFuncAttributeMaxDynamicSharedMemorySize, SMEM_DYN);
    cudaFuncSetAttribute(k_scores_mma, cudaFuncAttributeMaxDynamicSharedMemorySize, SMEM_DYN);
    cudaFuncSetAttribute(k_pv_mma,     cudaFuncAttributeMaxDynamicSharedMemorySize, SMEM_DYN);
    cudaFuncSetAttribute(k_out_mma,    cudaFuncAttributeMaxDynamicSharedMemorySize, SMEM_DYN);

    const int n4 = TT * DK / 4;
    k_dummy     <<<1, 32>>>();                                    // 1
    k_split_all <<<dim3(n4 / 256, 5), 256>>>(x, Wq, Wk, Wv, Wu);  // 2
    k_qkv_mma   <<<dim3(32, 32, 3),  256, SMEM_DYN>>>();          // 3
    k_scores_mma<<<dim3(136, 1, NH), 256, SMEM_DYN>>>();          // 4 <- ncu slot
    k_softmax   <<<NH * SS / 8, 256>>>();
    k_pv_mma    <<<dim3(4, 16, NH),  256, SMEM_DYN>>>();
    k_out_mma   <<<dim3(4, 32, 4),   256, SMEM_DYN>>>();
    k_reduce_out<<<(TT * 512 / 4) / 256, 256>>>(out);
}

// round 15
// speedup vs baseline: 3.8370x; 1.2959x over previous
#include <cuda_runtime.h>
#include <cuda_fp16.h>
#include <math_constants.h>
#include <cstdint>

#define BB 2
#define SS 2048
#define HH 8
#define DK 512
#define TT (BB*SS)      // 4096 tokens
#define NH (BB*HH)      // 16 (b,h) pairs

// ---------------- static device scratch (no allocs allowed) ----------------
__device__ __half g_x1[TT*512];                         // all operands hi-digit fp16
__device__ __half g_wq1[4096*512];
__device__ __half g_wk1[4096*512];
__device__ __half g_wv1[4096*512];
__device__ __half g_wu1[512*4096];
__device__ __half g_q1[NH*SS*DK];
__device__ __half g_k1[NH*SS*DK];
__device__ __half g_v1[NH*SS*DK];                       // natural [t][e]
__device__ float  g_s [(size_t)NH*SS*SS];               // fp32 scores (lower tri)
__device__ __half g_p1[(size_t)NH*SS*SS];
__device__ __half g_ho1[(size_t)TT*4096];
__device__ float  g_op[4][(size_t)TT*512];              // out k-split partials

// ---------------- helpers ----------------
__device__ __forceinline__ uint32_t smem_u32(const void* p){
    uint32_t a; asm("{ .reg .u64 t; cvta.to.shared.u64 t, %1; cvt.u32.u64 %0, t; }":"=r"(a):"l"(p)); return a;
}
__device__ __forceinline__ void ldsm4(uint32_t* r, uint32_t addr){
    asm volatile("ldmatrix.sync.aligned.m8n8.x4.shared.b16 {%0,%1,%2,%3}, [%4];"
        : "=r"(r[0]),"=r"(r[1]),"=r"(r[2]),"=r"(r[3]) : "r"(addr));
}
__device__ __forceinline__ void ldsm4t(uint32_t* r, uint32_t addr){
    asm volatile("ldmatrix.sync.aligned.m8n8.x4.trans.shared.b16 {%0,%1,%2,%3}, [%4];"
        : "=r"(r[0]),"=r"(r[1]),"=r"(r[2]),"=r"(r[3]) : "r"(addr));
}
__device__ __forceinline__ void mma_f16(float* c, const uint32_t* a, uint32_t b0, uint32_t b1){
    asm volatile("mma.sync.aligned.m16n8k16.row.col.f32.f16.f16.f32 "
        "{%0,%1,%2,%3}, {%4,%5,%6,%7}, {%8,%9}, {%0,%1,%2,%3};"
        : "+f"(c[0]),"+f"(c[1]),"+f"(c[2]),"+f"(c[3])
        : "r"(a[0]),"r"(a[1]),"r"(a[2]),"r"(a[3]), "r"(b0),"r"(b1));
}
__device__ __forceinline__ void cp16(uint32_t dst, const void* src){
    asm volatile("cp.async.cg.shared.global [%0], [%1], 16;" :: "r"(dst), "l"(src) : "memory");
}
#define CP_COMMIT() asm volatile("cp.async.commit_group;" ::: "memory")
template<int N> __device__ __forceinline__ void cp_wait(){
    asm volatile("cp.async.wait_group %0;" :: "n"(N) : "memory");
}
__device__ __forceinline__ uint32_t swzA(uint32_t row, uint32_t ch){
    return row * 64 + ((ch ^ ((row >> 1) & 3)) << 4);
}
__device__ __forceinline__ uint32_t swzB(uint32_t row, uint32_t ch){
    return row * 256 + ((ch ^ (row & 7)) << 4);
}

#define STAGE 16384u        // A 8K | B 8K
#define NSTAGE 3
#define SMEM_DYN (STAGE*NSTAGE)   // 49152

// ---------------------------------------------------------------------------
// fp16 1-term warp-MMA GEMM: D = scale * A1 . op(B1), fp32 accumulate.
// 3-stage cp.async, BK=32, block 128x128, 8 warps (4Mx2N), warp tile 32x64.
// BT=true: B[N,K] (NT).  BT=false: B[K,N] (NN, trans-ldsm).
// EPI: 0 fp32+causal-mask | 1 fp32 | 4 fp16 hi-only (O1)
// ---------------------------------------------------------------------------
template<int EPI, bool BT>
__device__ void gemm_mma(
    const __half* __restrict__ A1, int lda,
    const __half* __restrict__ B1, int ldb,
    int kCount, int m0, int n0, float scale,
    float* __restrict__ Cf, int ldc,
    __half* __restrict__ O1, int orow)
{
    extern __shared__ char sm[];
    const int tid = threadIdx.x, lane = tid & 31, wid = tid >> 5;
    const int wm = wid & 3, wn = wid >> 2;
    const int g = lane >> 2, t4 = lane & 3;
    const uint32_t sbase = smem_u32(sm);

    const int mtx = lane >> 3, ri = lane & 7;
    const int lrow = ((mtx & 1) << 3) + ri;
    const int lkh  = mtx >> 1;
    const int brow = ((lane >> 4) << 3) + ri;
    const int bchh = (lane >> 3) & 1;

    float acc[64];
#pragma unroll
    for (int i = 0; i < 64; i++) acc[i] = 0.f;

    const int nk = kCount >> 5;

    auto load_chunk = [&](int kc){
        const uint32_t sb = sbase + (uint32_t)(kc % NSTAGE) * STAGE;
        const int k0 = kc << 5;
#pragma unroll
        for (int i = 0; i < 2; i++) {          // A
            int lin = tid + i * 256;
            int r = lin >> 2, ch = lin & 3;
            cp16(sb + swzA(r, ch), A1 + (size_t)(m0 + r) * lda + k0 + ch * 8);
        }
        if (BT) {
#pragma unroll
            for (int i = 0; i < 2; i++) {      // B[N,K]
                int lin = tid + i * 256;
                int r = lin >> 2, ch = lin & 3;
                cp16(sb + 8192 + swzA(r, ch), B1 + (size_t)(n0 + r) * ldb + k0 + ch * 8);
            }
        } else {
#pragma unroll
            for (int i = 0; i < 2; i++) {      // B[K,N]: 32 rows x 256B
                int lin = tid + i * 256;
                int r = lin >> 4, ch = lin & 15;
                cp16(sb + 8192 + swzB(r, ch), B1 + (size_t)(k0 + r) * ldb + n0 + ch * 8);
            }
        }
    };

    load_chunk(0);            CP_COMMIT();
    if (nk > 1) load_chunk(1);
    CP_COMMIT();

    for (int kc = 0; kc < nk; kc++) {
        if (kc + 2 < nk) load_chunk(kc + 2);
        CP_COMMIT();
        cp_wait<2>();
        __syncthreads();

        const uint32_t cb = sbase + (uint32_t)(kc % NSTAGE) * STAGE;
#pragma unroll
        for (int kk = 0; kk < 2; kk++) {
            const int ch = kk * 2 + lkh;
            uint32_t aH[8];
#pragma unroll
            for (int s = 0; s < 2; s++) {
                uint32_t off = swzA((uint32_t)(wm * 32 + s * 16 + lrow), ch);
                ldsm4(aH + s * 4, cb + off);
            }
#pragma unroll
            for (int nbp = 0; nbp < 2; nbp++) {
                uint32_t bh[8];
#pragma unroll
                for (int q = 0; q < 2; q++) {
                    int nb = nbp * 2 + q;
                    if (BT) {
                        uint32_t off = swzA((uint32_t)(wn * 64 + nb * 16 + lrow), ch);
                        ldsm4(bh + q * 4, cb + 8192 + off);
                    } else {
                        uint32_t off = swzB((uint32_t)(kk * 16 + brow),
                                            (uint32_t)(wn * 8 + nb * 2 + bchh));
                        ldsm4t(bh + q * 4, cb + 8192 + off);
                    }
                }
#pragma unroll
                for (int q = 0; q < 2; q++) {
#pragma unroll
                    for (int mi = 0; mi < 2; mi++) {
#pragma unroll
                        for (int sub = 0; sub < 2; sub++) {
                            int nb = nbp * 2 + q;
                            float* c = acc + (mi * 8 + nb * 2 + sub) * 4;
                            mma_f16(c, aH + mi * 4, bh[q * 4 + sub], bh[q * 4 + sub + 2]);
                        }
                    }
                }
            }
        }
        __syncthreads();
    }

    // ---- epilogue
#pragma unroll
    for (int mi = 0; mi < 2; mi++) {
#pragma unroll
        for (int nbi = 0; nbi < 8; nbi++) {
            const float* c = acc + (mi * 8 + nbi) * 4;
            int rl = wm * 32 + mi * 16 + g;
            int cl = wn * 64 + nbi * 8 + 2 * t4;
            if (EPI <= 1) {
                int gr0 = m0 + rl, gc = n0 + cl;
                float v0 = c[0] * scale, v1 = c[1] * scale;
                float v2 = c[2] * scale, v3 = c[3] * scale;
                if (EPI == 0) {
                    if (gc     > gr0)     v0 = -CUDART_INF_F;
                    if (gc + 1 > gr0)     v1 = -CUDART_INF_F;
                    if (gc     > gr0 + 8) v2 = -CUDART_INF_F;
                    if (gc + 1 > gr0 + 8) v3 = -CUDART_INF_F;
                }
                *reinterpret_cast<float2*>(Cf + (size_t)gr0 * ldc + gc)       = make_float2(v0, v1);
                *reinterpret_cast<float2*>(Cf + (size_t)(gr0 + 8) * ldc + gc) = make_float2(v2, v3);
            } else {
                size_t gm = (size_t)(m0 + rl);
                size_t o0 = gm * orow + cl, o1 = o0 + (size_t)8 * orow;
                *reinterpret_cast<__half2*>(O1 + o0) =
                    __half2(__float2half(c[0]), __float2half(c[1]));
                *reinterpret_cast<__half2*>(O1 + o1) =
                    __half2(__float2half(c[2]), __float2half(c[3]));
            }
        }
    }
}

// ---------------------------------------------------------------------------
__global__ void k_dummy(void) {}   // keeps scores in the ncu capture slot

// hi-digit fp16 conversion for all 5 inputs
__global__ void __launch_bounds__(256) k_split_all(
    const float* __restrict__ x,  const float* __restrict__ Wq,
    const float* __restrict__ Wk, const float* __restrict__ Wv,
    const float* __restrict__ Wu)
{
    const int z = blockIdx.y;
    const float* s;
    __half* h;
    switch (z) {
        case 0: s = x;  h = g_x1;  break;
        case 1: s = Wq; h = g_wq1; break;
        case 2: s = Wk; h = g_wk1; break;
        case 3: s = Wv; h = g_wv1; break;
        default: s = Wu; h = g_wu1; break;
    }
    int i = blockIdx.x * blockDim.x + threadIdx.x;
    float4 v = reinterpret_cast<const float4*>(s)[i];
    __half h0=__float2half(v.x), h1=__float2half(v.y),
           h2=__float2half(v.z), h3=__float2half(v.w);
    reinterpret_cast<uint2*>(h)[i] = make_uint2(
        (uint32_t)__half_as_ushort(h0)|((uint32_t)__half_as_ushort(h1)<<16),
        (uint32_t)__half_as_ushort(h2)|((uint32_t)__half_as_ushort(h3)<<16));
}

// QKV: 1-term x1 . W1, hi-only outputs for q, k, v.
__global__ void __launch_bounds__(256, 2) k_qkv_mma(void)
{
    int n0 = blockIdx.x * 128, m0 = blockIdx.y * 128, z = blockIdx.z;
    int b = m0 >> 11, h = n0 >> 9, e0 = n0 & 511;
    size_t base = ((size_t)(b * HH + h) * SS) * DK + e0 - (size_t)(b * SS) * DK;
    const __half* W = (z == 0) ? g_wq1 : (z == 1) ? g_wk1 : g_wv1;
    __half* O      = (z == 0) ? g_q1  : (z == 1) ? g_k1  : g_v1;
    gemm_mma<4, true>(g_x1, 512, W, 512, 512, m0, n0, 1.f, nullptr, 0, O + base, 512);
}

// Scores: 1-term q1 x k1. Triangular grid over lower-tri tiles.
__global__ void __launch_bounds__(256, 2) k_scores_mma(void)
{
    int t = blockIdx.x, bh = blockIdx.z;
    int r = (int)((sqrtf(8.f * t + 1.f) - 1.f) * 0.5f);
    while ((r + 1) * (r + 2) / 2 <= t) r++;
    while (r * (r + 1) / 2 > t) r--;
    int c = t - r * (r + 1) / 2;
    int m0 = r * 128, n0 = c * 128;
    float* Cf = g_s + (size_t)bh * SS * SS;
    size_t ob = (size_t)bh * SS * DK;
    gemm_mma<0, true>(g_q1 + ob, 512, g_k1 + ob, 512,
                      512, m0, n0, 0.04419417382415922f, Cf, SS, nullptr, 0);
}

__global__ void __launch_bounds__(256) k_softmax(void)
{
    int row  = blockIdx.x * 8 + (threadIdx.x >> 5);
    int lane = threadIdx.x & 31;
    int r    = row & (SS - 1);
    int rt   = r >> 7;
    const float4* p = reinterpret_cast<const float4*>(g_s + (size_t)row * SS);
    uint2* p1 = reinterpret_cast<uint2*>(g_p1 + (size_t)row * SS);

    float4 v[16];
    float mx = -CUDART_INF_F;
#pragma unroll
    for (int i = 0; i < 16; i++) {
        if (i <= rt) {
            v[i] = p[lane + i * 32];
            mx = fmaxf(mx, fmaxf(fmaxf(v[i].x, v[i].y), fmaxf(v[i].z, v[i].w)));
        }
    }
#pragma unroll
    for (int o = 16; o; o >>= 1) mx = fmaxf(mx, __shfl_xor_sync(0xffffffffu, mx, o));
    float sum = 0.0f;
#pragma unroll
    for (int i = 0; i < 16; i++) {
        if (i > rt) continue;
        v[i].x = __expf(v[i].x - mx); v[i].y = __expf(v[i].y - mx);
        v[i].z = __expf(v[i].z - mx); v[i].w = __expf(v[i].w - mx);
        sum += (v[i].x + v[i].y) + (v[i].z + v[i].w);
    }
#pragma unroll
    for (int o = 16; o; o >>= 1) sum += __shfl_xor_sync(0xffffffffu, sum, o);
    float inv = 1.0f / sum;
#pragma unroll
    for (int i = 0; i < 16; i++) {
        if (i > rt) continue;
        __half h0=__float2half(v[i].x*inv), h1=__float2half(v[i].y*inv),
               h2=__float2half(v[i].z*inv), h3=__float2half(v[i].w*inv);
        p1[lane + i*32] = make_uint2(
            (uint32_t)__half_as_ushort(h0)|((uint32_t)__half_as_ushort(h1)<<16),
            (uint32_t)__half_as_ushort(h2)|((uint32_t)__half_as_ushort(h3)<<16));
    }
}

// PV: 1-term p1 x v1 (NN). Heavy-first m tiles. hi-only ho output.
__global__ void __launch_bounds__(256, 2) k_pv_mma(void)
{
    int bh = blockIdx.z, b = bh >> 3, h = bh & 7;
    int m0 = (15 - blockIdx.y) * 128;
    int n0 = blockIdx.x * 128;
    const __half* A1 = g_p1 + (size_t)bh * SS * SS;
    const __half* B1 = g_v1 + (size_t)bh * SS * DK;
    size_t base = (size_t)b * SS * 4096 + h * 512 + n0;
    gemm_mma<4, false>(A1, SS, B1, 512, m0 + 128, m0, n0, 1.f,
                       nullptr, 0, g_ho1 + base, 4096);
}

// out GEMM: 1-term ho1 x Wu1, k-split into 4 slices.
__global__ void __launch_bounds__(256, 2) k_out_mma(void)
{
    int m0 = blockIdx.y * 128, n0 = blockIdx.x * 128, sl = blockIdx.z;
    int koff = sl * 1024;
    gemm_mma<1, true>(g_ho1 + koff, 4096, g_wu1 + koff, 4096,
                      1024, m0, n0, 1.f, g_op[sl], 512, nullptr, 0);
}

__global__ void __launch_bounds__(256) k_reduce_out(float* __restrict__ out)
{
    int i = blockIdx.x * blockDim.x + threadIdx.x;
    float4 a = reinterpret_cast<const float4*>(g_op[0])[i];
    float4 b = reinterpret_cast<const float4*>(g_op[1])[i];
    float4 c = reinterpret_cast<const float4*>(g_op[2])[i];
    float4 d = reinterpret_cast<const float4*>(g_op[3])[i];
    float4 o;
    o.x = (a.x + b.x) + (c.x + d.x);
    o.y = (a.y + b.y) + (c.y + d.y);
    o.z = (a.z + b.z) + (c.z + d.z);
    o.w = (a.w + b.w) + (c.w + d.w);
    reinterpret_cast<float4*>(out)[i] = o;
}

// ---------------------------------------------------------------------------
extern "C" void kernel_launch(void* const* d_in, const int* in_sizes, int n_in,
                              void* d_out, int out_size)
{
    const float* x  = (const float*)d_in[0];
    const float* Wq = (const float*)d_in[1];
    const float* Wk = (const float*)d_in[2];
    const float* Wv = (const float*)d_in[3];
    const float* Wu = (const float*)d_in[4];
    float* out = (float*)d_out;

    cudaFuncSetAttribute(k_qkv_mma,    cudaFuncAttributeMaxDynamicSharedMemorySize, SMEM_DYN);
    cudaFuncSetAttribute(k_scores_mma, cudaFuncAttributeMaxDynamicSharedMemorySize, SMEM_DYN);
    cudaFuncSetAttribute(k_pv_mma,     cudaFuncAttributeMaxDynamicSharedMemorySize, SMEM_DYN);
    cudaFuncSetAttribute(k_out_mma,    cudaFuncAttributeMaxDynamicSharedMemorySize, SMEM_DYN);

    const int n4 = TT * DK / 4;
    k_dummy     <<<1, 32>>>();                                    // 1
    k_split_all <<<dim3(n4 / 256, 5), 256>>>(x, Wq, Wk, Wv, Wu);  // 2
    k_qkv_mma   <<<dim3(32, 32, 3),  256, SMEM_DYN>>>();          // 3
    k_scores_mma<<<dim3(136, 1, NH), 256, SMEM_DYN>>>();          // 4 <- ncu slot
    k_softmax   <<<NH * SS / 8, 256>>>();
    k_pv_mma    <<<dim3(4, 16, NH),  256, SMEM_DYN>>>();
    k_out_mma   <<<dim3(4, 32, 4),   256, SMEM_DYN>>>();
    k_reduce_out<<<(TT * 512 / 4) / 256, 256>>>(out);
}

// round 16
// speedup vs baseline: 3.8894x; 1.0136x over previous
#include <cuda_runtime.h>
#include <cuda_fp16.h>
#include <math_constants.h>
#include <cstdint>

#define BB 2
#define SS 2048
#define HH 8
#define DK 512
#define TT (BB*SS)      // 4096 tokens
#define NH (BB*HH)      // 16 (b,h) pairs

// ---------------- static device scratch (no allocs allowed) ----------------
__device__ __half g_x1[TT*512];
__device__ __half g_wq1[4096*512];
__device__ __half g_wk1[4096*512];
__device__ __half g_wv1[4096*512];
__device__ __half g_wu1[512*4096];
__device__ __half g_q1[NH*SS*DK];
__device__ __half g_k1[NH*SS*DK];
__device__ __half g_v1[NH*SS*DK];                       // natural [t][e]
__device__ __half g_sh[(size_t)NH*SS*SS];               // fp16 scores (lower tri)
__device__ __half g_p1[(size_t)NH*SS*SS];
__device__ __half g_ho1[(size_t)TT*4096];
__device__ float  g_op[4][(size_t)TT*512];              // out k-split partials

// ---------------- helpers ----------------
__device__ __forceinline__ uint32_t smem_u32(const void* p){
    uint32_t a; asm("{ .reg .u64 t; cvta.to.shared.u64 t, %1; cvt.u32.u64 %0, t; }":"=r"(a):"l"(p)); return a;
}
__device__ __forceinline__ void ldsm4(uint32_t* r, uint32_t addr){
    asm volatile("ldmatrix.sync.aligned.m8n8.x4.shared.b16 {%0,%1,%2,%3}, [%4];"
        : "=r"(r[0]),"=r"(r[1]),"=r"(r[2]),"=r"(r[3]) : "r"(addr));
}
__device__ __forceinline__ void ldsm4t(uint32_t* r, uint32_t addr){
    asm volatile("ldmatrix.sync.aligned.m8n8.x4.trans.shared.b16 {%0,%1,%2,%3}, [%4];"
        : "=r"(r[0]),"=r"(r[1]),"=r"(r[2]),"=r"(r[3]) : "r"(addr));
}
__device__ __forceinline__ void mma_f16(float* c, const uint32_t* a, uint32_t b0, uint32_t b1){
    asm volatile("mma.sync.aligned.m16n8k16.row.col.f32.f16.f16.f32 "
        "{%0,%1,%2,%3}, {%4,%5,%6,%7}, {%8,%9}, {%0,%1,%2,%3};"
        : "+f"(c[0]),"+f"(c[1]),"+f"(c[2]),"+f"(c[3])
        : "r"(a[0]),"r"(a[1]),"r"(a[2]),"r"(a[3]), "r"(b0),"r"(b1));
}
__device__ __forceinline__ void cp16(uint32_t dst, const void* src){
    asm volatile("cp.async.cg.shared.global [%0], [%1], 16;" :: "r"(dst), "l"(src) : "memory");
}
#define CP_COMMIT() asm volatile("cp.async.commit_group;" ::: "memory")
template<int N> __device__ __forceinline__ void cp_wait(){
    asm volatile("cp.async.wait_group %0;" :: "n"(N) : "memory");
}
__device__ __forceinline__ uint32_t swzA(uint32_t row, uint32_t ch){
    return row * 64 + ((ch ^ ((row >> 1) & 3)) << 4);
}
__device__ __forceinline__ uint32_t swzB(uint32_t row, uint32_t ch){
    return row * 256 + ((ch ^ (row & 7)) << 4);
}

#define STAGE 16384u        // A 8K | B 8K
#define NSTAGE 3
#define SMEM_DYN (STAGE*NSTAGE)   // 49152

// ---------------------------------------------------------------------------
// fp16 1-term warp-MMA GEMM, 512 threads / 16 warps (4Mx4N), warp tile 32x32,
// BK=32, 3-stage cp.async, __launch_bounds__(512,2) -> 32 warps/SM.
// D = scale * A1 . op(B1), fp32 accumulate.
// BT=true: B[N,K] (NT).  BT=false: B[K,N] (NN, trans-ldsm).
// EPI: 0 fp16 store + causal mask | 1 fp32 store | 4 fp16 hi-only (O1)
// ---------------------------------------------------------------------------
template<int EPI, bool BT>
__device__ void gemm_mma(
    const __half* __restrict__ A1, int lda,
    const __half* __restrict__ B1, int ldb,
    int kCount, int m0, int n0, float scale,
    float* __restrict__ Cf, __half* __restrict__ Ch, int ldc,
    __half* __restrict__ O1, int orow)
{
    extern __shared__ char sm[];
    const int tid = threadIdx.x, lane = tid & 31, wid = tid >> 5;
    const int wm = wid & 3, wn = wid >> 2;      // 4M x 4N warp grid
    const int g = lane >> 2, t4 = lane & 3;
    const uint32_t sbase = smem_u32(sm);

    const int mtx = lane >> 3, ri = lane & 7;
    const int lrow = ((mtx & 1) << 3) + ri;
    const int lkh  = mtx >> 1;
    const int brow = ((lane >> 4) << 3) + ri;
    const int bchh = (lane >> 3) & 1;

    float acc[32];
#pragma unroll
    for (int i = 0; i < 32; i++) acc[i] = 0.f;

    const int nk = kCount >> 5;

    auto load_chunk = [&](int kc){
        const uint32_t sb = sbase + (uint32_t)(kc % NSTAGE) * STAGE;
        const int k0 = kc << 5;
        {   // A: 128 rows x 64B, 1 cp16/thread
            int r = tid >> 2, ch = tid & 3;
            cp16(sb + swzA(r, ch), A1 + (size_t)(m0 + r) * lda + k0 + ch * 8);
        }
        if (BT) {
            int r = tid >> 2, ch = tid & 3;
            cp16(sb + 8192 + swzA(r, ch), B1 + (size_t)(n0 + r) * ldb + k0 + ch * 8);
        } else {
            int r = tid >> 4, ch = tid & 15;   // 32 rows x 256B
            cp16(sb + 8192 + swzB(r, ch), B1 + (size_t)(k0 + r) * ldb + n0 + ch * 8);
        }
    };

    load_chunk(0);            CP_COMMIT();
    if (nk > 1) load_chunk(1);
    CP_COMMIT();

    for (int kc = 0; kc < nk; kc++) {
        if (kc + 2 < nk) load_chunk(kc + 2);
        CP_COMMIT();
        cp_wait<2>();
        __syncthreads();

        const uint32_t cb = sbase + (uint32_t)(kc % NSTAGE) * STAGE;
#pragma unroll
        for (int kk = 0; kk < 2; kk++) {
            const int ch = kk * 2 + lkh;
            uint32_t aH[8];
#pragma unroll
            for (int s = 0; s < 2; s++) {
                uint32_t off = swzA((uint32_t)(wm * 32 + s * 16 + lrow), ch);
                ldsm4(aH + s * 4, cb + off);
            }
#pragma unroll
            for (int q = 0; q < 2; q++) {       // two 16-col B tiles
                uint32_t bh[4];
                if (BT) {
                    uint32_t off = swzA((uint32_t)(wn * 32 + q * 16 + lrow), ch);
                    ldsm4(bh, cb + 8192 + off);
                } else {
                    uint32_t off = swzB((uint32_t)(kk * 16 + brow),
                                        (uint32_t)(wn * 4 + q * 2 + bchh));
                    ldsm4t(bh, cb + 8192 + off);
                }
#pragma unroll
                for (int mi = 0; mi < 2; mi++) {
#pragma unroll
                    for (int sub = 0; sub < 2; sub++) {
                        float* c = acc + (mi * 4 + q * 2 + sub) * 4;
                        mma_f16(c, aH + mi * 4, bh[sub], bh[sub + 2]);
                    }
                }
            }
        }
        __syncthreads();
    }

    // ---- epilogue
#pragma unroll
    for (int mi = 0; mi < 2; mi++) {
#pragma unroll
        for (int nbi = 0; nbi < 4; nbi++) {
            const float* c = acc + (mi * 4 + nbi) * 4;
            int rl = wm * 32 + mi * 16 + g;
            int cl = wn * 32 + nbi * 8 + 2 * t4;
            if (EPI == 0) {
                int gr0 = m0 + rl, gc = n0 + cl;
                float v0 = c[0] * scale, v1 = c[1] * scale;
                float v2 = c[2] * scale, v3 = c[3] * scale;
                if (gc     > gr0)     v0 = -CUDART_INF_F;
                if (gc + 1 > gr0)     v1 = -CUDART_INF_F;
                if (gc     > gr0 + 8) v2 = -CUDART_INF_F;
                if (gc + 1 > gr0 + 8) v3 = -CUDART_INF_F;
                *reinterpret_cast<__half2*>(Ch + (size_t)gr0 * ldc + gc) =
                    __half2(__float2half(v0), __float2half(v1));
                *reinterpret_cast<__half2*>(Ch + (size_t)(gr0 + 8) * ldc + gc) =
                    __half2(__float2half(v2), __float2half(v3));
            } else if (EPI == 1) {
                int gr0 = m0 + rl, gc = n0 + cl;
                *reinterpret_cast<float2*>(Cf + (size_t)gr0 * ldc + gc)       = make_float2(c[0], c[1]);
                *reinterpret_cast<float2*>(Cf + (size_t)(gr0 + 8) * ldc + gc) = make_float2(c[2], c[3]);
            } else {
                size_t gm = (size_t)(m0 + rl);
                size_t o0 = gm * orow + cl, o1 = o0 + (size_t)8 * orow;
                *reinterpret_cast<__half2*>(O1 + o0) =
                    __half2(__float2half(c[0]), __float2half(c[1]));
                *reinterpret_cast<__half2*>(O1 + o1) =
                    __half2(__float2half(c[2]), __float2half(c[3]));
            }
        }
    }
}

// ---------------------------------------------------------------------------
__global__ void k_dummy(void) {}   // keeps scores in the ncu capture slot

__global__ void __launch_bounds__(256) k_split_all(
    const float* __restrict__ x,  const float* __restrict__ Wq,
    const float* __restrict__ Wk, const float* __restrict__ Wv,
    const float* __restrict__ Wu)
{
    const int z = blockIdx.y;
    const float* s;
    __half* h;
    switch (z) {
        case 0: s = x;  h = g_x1;  break;
        case 1: s = Wq; h = g_wq1; break;
        case 2: s = Wk; h = g_wk1; break;
        case 3: s = Wv; h = g_wv1; break;
        default: s = Wu; h = g_wu1; break;
    }
    int i = blockIdx.x * blockDim.x + threadIdx.x;
    float4 v = reinterpret_cast<const float4*>(s)[i];
    __half h0=__float2half(v.x), h1=__float2half(v.y),
           h2=__float2half(v.z), h3=__float2half(v.w);
    reinterpret_cast<uint2*>(h)[i] = make_uint2(
        (uint32_t)__half_as_ushort(h0)|((uint32_t)__half_as_ushort(h1)<<16),
        (uint32_t)__half_as_ushort(h2)|((uint32_t)__half_as_ushort(h3)<<16));
}

// QKV: 1-term x1 . W1, hi-only outputs for q, k, v.
__global__ void __launch_bounds__(512, 2) k_qkv_mma(void)
{
    int n0 = blockIdx.x * 128, m0 = blockIdx.y * 128, z = blockIdx.z;
    int b = m0 >> 11, h = n0 >> 9, e0 = n0 & 511;
    size_t base = ((size_t)(b * HH + h) * SS) * DK + e0 - (size_t)(b * SS) * DK;
    const __half* W = (z == 0) ? g_wq1 : (z == 1) ? g_wk1 : g_wv1;
    __half* O      = (z == 0) ? g_q1  : (z == 1) ? g_k1  : g_v1;
    gemm_mma<4, true>(g_x1, 512, W, 512, 512, m0, n0, 1.f,
                      nullptr, nullptr, 0, O + base, 512);
}

// Scores: 1-term q1 x k1, fp16 output. Triangular grid.
__global__ void __launch_bounds__(512, 2) k_scores_mma(void)
{
    int t = blockIdx.x, bh = blockIdx.z;
    int r = (int)((sqrtf(8.f * t + 1.f) - 1.f) * 0.5f);
    while ((r + 1) * (r + 2) / 2 <= t) r++;
    while (r * (r + 1) / 2 > t) r--;
    int c = t - r * (r + 1) / 2;
    int m0 = r * 128, n0 = c * 128;
    __half* Ch = g_sh + (size_t)bh * SS * SS;
    size_t ob = (size_t)bh * SS * DK;
    gemm_mma<0, true>(g_q1 + ob, 512, g_k1 + ob, 512,
                      512, m0, n0, 0.04419417382415922f,
                      nullptr, Ch, SS, nullptr, 0);
}

// Softmax over fp16 scores; emits fp16 probs.
__global__ void __launch_bounds__(256) k_softmax(void)
{
    int row  = blockIdx.x * 8 + (threadIdx.x >> 5);
    int lane = threadIdx.x & 31;
    int r    = row & (SS - 1);
    int rt   = r >> 7;
    const uint2* p = reinterpret_cast<const uint2*>(g_sh + (size_t)row * SS);
    uint2* p1 = reinterpret_cast<uint2*>(g_p1 + (size_t)row * SS);

    float4 v[16];
    float mx = -CUDART_INF_F;
#pragma unroll
    for (int i = 0; i < 16; i++) {
        if (i <= rt) {
            uint2 u = p[lane + i * 32];
            __half2 a = *reinterpret_cast<__half2*>(&u.x);
            __half2 b = *reinterpret_cast<__half2*>(&u.y);
            v[i] = make_float4(__half2float(a.x), __half2float(a.y),
                               __half2float(b.x), __half2float(b.y));
            mx = fmaxf(mx, fmaxf(fmaxf(v[i].x, v[i].y), fmaxf(v[i].z, v[i].w)));
        }
    }
#pragma unroll
    for (int o = 16; o; o >>= 1) mx = fmaxf(mx, __shfl_xor_sync(0xffffffffu, mx, o));
    float sum = 0.0f;
#pragma unroll
    for (int i = 0; i < 16; i++) {
        if (i > rt) continue;
        v[i].x = __expf(v[i].x - mx); v[i].y = __expf(v[i].y - mx);
        v[i].z = __expf(v[i].z - mx); v[i].w = __expf(v[i].w - mx);
        sum += (v[i].x + v[i].y) + (v[i].z + v[i].w);
    }
#pragma unroll
    for (int o = 16; o; o >>= 1) sum += __shfl_xor_sync(0xffffffffu, sum, o);
    float inv = 1.0f / sum;
#pragma unroll
    for (int i = 0; i < 16; i++) {
        if (i > rt) continue;
        __half h0=__float2half(v[i].x*inv), h1=__float2half(v[i].y*inv),
               h2=__float2half(v[i].z*inv), h3=__float2half(v[i].w*inv);
        p1[lane + i*32] = make_uint2(
            (uint32_t)__half_as_ushort(h0)|((uint32_t)__half_as_ushort(h1)<<16),
            (uint32_t)__half_as_ushort(h2)|((uint32_t)__half_as_ushort(h3)<<16));
    }
}

// PV: 1-term p1 x v1 (NN). Heavy-first m tiles. hi-only ho output.
__global__ void __launch_bounds__(512, 2) k_pv_mma(void)
{
    int bh = blockIdx.z, b = bh >> 3, h = bh & 7;
    int m0 = (15 - blockIdx.y) * 128;
    int n0 = blockIdx.x * 128;
    const __half* A1 = g_p1 + (size_t)bh * SS * SS;
    const __half* B1 = g_v1 + (size_t)bh * SS * DK;
    size_t base = (size_t)b * SS * 4096 + h * 512 + n0;
    gemm_mma<4, false>(A1, SS, B1, 512, m0 + 128, m0, n0, 1.f,
                       nullptr, nullptr, 0, g_ho1 + base, 4096);
}

// out GEMM: 1-term ho1 x Wu1, k-split into 4 slices, fp32 partials.
__global__ void __launch_bounds__(512, 2) k_out_mma(void)
{
    int m0 = blockIdx.y * 128, n0 = blockIdx.x * 128, sl = blockIdx.z;
    int koff = sl * 1024;
    gemm_mma<1, true>(g_ho1 + koff, 4096, g_wu1 + koff, 4096,
                      1024, m0, n0, 1.f, g_op[sl], nullptr, 512, nullptr, 0);
}

__global__ void __launch_bounds__(256) k_reduce_out(float* __restrict__ out)
{
    int i = blockIdx.x * blockDim.x + threadIdx.x;
    float4 a = reinterpret_cast<const float4*>(g_op[0])[i];
    float4 b = reinterpret_cast<const float4*>(g_op[1])[i];
    float4 c = reinterpret_cast<const float4*>(g_op[2])[i];
    float4 d = reinterpret_cast<const float4*>(g_op[3])[i];
    float4 o;
    o.x = (a.x + b.x) + (c.x + d.x);
    o.y = (a.y + b.y) + (c.y + d.y);
    o.z = (a.z + b.z) + (c.z + d.z);
    o.w = (a.w + b.w) + (c.w + d.w);
    reinterpret_cast<float4*>(out)[i] = o;
}

// ---------------------------------------------------------------------------
extern "C" void kernel_launch(void* const* d_in, const int* in_sizes, int n_in,
                              void* d_out, int out_size)
{
    const float* x  = (const float*)d_in[0];
    const float* Wq = (const float*)d_in[1];
    const float* Wk = (const float*)d_in[2];
    const float* Wv = (const float*)d_in[3];
    const float* Wu = (const float*)d_in[4];
    float* out = (float*)d_out;

    cudaFuncSetAttribute(k_qkv_mma,    cudaFuncAttributeMaxDynamicSharedMemorySize, SMEM_DYN);
    cudaFuncSetAttribute(k_scores_mma, cudaFuncAttributeMaxDynamicSharedMemorySize, SMEM_DYN);
    cudaFuncSetAttribute(k_pv_mma,     cudaFuncAttributeMaxDynamicSharedMemorySize, SMEM_DYN);
    cudaFuncSetAttribute(k_out_mma,    cudaFuncAttributeMaxDynamicSharedMemorySize, SMEM_DYN);

    const int n4 = TT * DK / 4;
    k_dummy     <<<1, 32>>>();                                    // 1
    k_split_all <<<dim3(n4 / 256, 5), 256>>>(x, Wq, Wk, Wv, Wu);  // 2
    k_qkv_mma   <<<dim3(32, 32, 3),  512, SMEM_DYN>>>();          // 3
    k_scores_mma<<<dim3(136, 1, NH), 512, SMEM_DYN>>>();          // 4 <- ncu slot
    k_softmax   <<<NH * SS / 8, 256>>>();
    k_pv_mma    <<<dim3(4, 16, NH),  512, SMEM_DYN>>>();
    k_out_mma   <<<dim3(4, 32, 4),   512, SMEM_DYN>>>();
    k_reduce_out<<<(TT * 512 / 4) / 256, 256>>>(out);
}

// round 17
// speedup vs baseline: 4.0286x; 1.0358x over previous
#include <cuda_runtime.h>
#include <cuda_fp16.h>
#include <math_constants.h>
#include <cstdint>

#define BB 2
#define SS 2048
#define HH 8
#define DK 512
#define TT (BB*SS)      // 4096 tokens
#define NH (BB*HH)      // 16 (b,h) pairs

// ---------------- static device scratch (no allocs allowed) ----------------
__device__ __half g_x1[TT*512];
__device__ __half g_wq1[4096*512];
__device__ __half g_wk1[4096*512];
__device__ __half g_wv1[4096*512];
__device__ __half g_wu1[512*4096];
__device__ __half g_q1[NH*SS*DK];
__device__ __half g_k1[NH*SS*DK];
__device__ __half g_v1[NH*SS*DK];                       // natural [t][e]
__device__ __half g_p1[(size_t)NH*SS*SS];               // P~ = exp(s) fp16 (lower tri)
__device__ float  g_rs[(size_t)NH*16*4*SS];             // partial row sums [bh][tn][wn][row]
__device__ float  g_rinv[NH*SS];                        // 1 / rowsum
__device__ __half g_ho1[(size_t)TT*4096];
__device__ float  g_op[4][(size_t)TT*512];              // out k-split partials

// ---------------- helpers ----------------
__device__ __forceinline__ uint32_t smem_u32(const void* p){
    uint32_t a; asm("{ .reg .u64 t; cvta.to.shared.u64 t, %1; cvt.u32.u64 %0, t; }":"=r"(a):"l"(p)); return a;
}
__device__ __forceinline__ void ldsm4(uint32_t* r, uint32_t addr){
    asm volatile("ldmatrix.sync.aligned.m8n8.x4.shared.b16 {%0,%1,%2,%3}, [%4];"
        : "=r"(r[0]),"=r"(r[1]),"=r"(r[2]),"=r"(r[3]) : "r"(addr));
}
__device__ __forceinline__ void ldsm4t(uint32_t* r, uint32_t addr){
    asm volatile("ldmatrix.sync.aligned.m8n8.x4.trans.shared.b16 {%0,%1,%2,%3}, [%4];"
        : "=r"(r[0]),"=r"(r[1]),"=r"(r[2]),"=r"(r[3]) : "r"(addr));
}
__device__ __forceinline__ void mma_f16(float* c, const uint32_t* a, uint32_t b0, uint32_t b1){
    asm volatile("mma.sync.aligned.m16n8k16.row.col.f32.f16.f16.f32 "
        "{%0,%1,%2,%3}, {%4,%5,%6,%7}, {%8,%9}, {%0,%1,%2,%3};"
        : "+f"(c[0]),"+f"(c[1]),"+f"(c[2]),"+f"(c[3])
        : "r"(a[0]),"r"(a[1]),"r"(a[2]),"r"(a[3]), "r"(b0),"r"(b1));
}
__device__ __forceinline__ void cp16(uint32_t dst, const void* src){
    asm volatile("cp.async.cg.shared.global [%0], [%1], 16;" :: "r"(dst), "l"(src) : "memory");
}
#define CP_COMMIT() asm volatile("cp.async.commit_group;" ::: "memory")
template<int N> __device__ __forceinline__ void cp_wait(){
    asm volatile("cp.async.wait_group %0;" :: "n"(N) : "memory");
}
__device__ __forceinline__ uint32_t swzA(uint32_t row, uint32_t ch){
    return row * 64 + ((ch ^ ((row >> 1) & 3)) << 4);
}
__device__ __forceinline__ uint32_t swzB(uint32_t row, uint32_t ch){
    return row * 256 + ((ch ^ (row & 7)) << 4);
}

#define STAGE 16384u        // A 8K | B 8K
#define NSTAGE 3
#define SMEM_DYN (STAGE*NSTAGE)   // 49152

// ---------------------------------------------------------------------------
// fp16 1-term warp-MMA GEMM, 512 thr / 16 warps (4Mx4N), warp tile 32x32,
// BK=32, 3-stage cp.async, __launch_bounds__(512,2) -> 32 warps/SM.
// D = A1 . op(B1), fp32 accumulate.
// BT=true: B[N,K] (NT).  BT=false: B[K,N] (NN, trans-ldsm).
// EPI: 0 exp(s*scale)+mask -> fp16 Ch, partial row sums -> rs
//      1 fp32 -> Cf | 4 fp16 -> O1 | 5 fp16 (v * rs[row]) -> O1
// ---------------------------------------------------------------------------
template<int EPI, bool BT>
__device__ void gemm_mma(
    const __half* __restrict__ A1, int lda,
    const __half* __restrict__ B1, int ldb,
    int kCount, int m0, int n0, float scale,
    float* __restrict__ Cf, __half* __restrict__ Ch, int ldc,
    __half* __restrict__ O1, int orow, float* __restrict__ rs)
{
    extern __shared__ char sm[];
    const int tid = threadIdx.x, lane = tid & 31, wid = tid >> 5;
    const int wm = wid & 3, wn = wid >> 2;      // 4M x 4N warp grid
    const int g = lane >> 2, t4 = lane & 3;
    const uint32_t sbase = smem_u32(sm);

    const int mtx = lane >> 3, ri = lane & 7;
    const int lrow = ((mtx & 1) << 3) + ri;
    const int lkh  = mtx >> 1;
    const int brow = ((lane >> 4) << 3) + ri;
    const int bchh = (lane >> 3) & 1;

    float acc[32];
#pragma unroll
    for (int i = 0; i < 32; i++) acc[i] = 0.f;

    const int nk = kCount >> 5;

    auto load_chunk = [&](int kc){
        const uint32_t sb = sbase + (uint32_t)(kc % NSTAGE) * STAGE;
        const int k0 = kc << 5;
        {   // A: 128 rows x 64B, 1 cp16/thread
            int r = tid >> 2, ch = tid & 3;
            cp16(sb + swzA(r, ch), A1 + (size_t)(m0 + r) * lda + k0 + ch * 8);
        }
        if (BT) {
            int r = tid >> 2, ch = tid & 3;
            cp16(sb + 8192 + swzA(r, ch), B1 + (size_t)(n0 + r) * ldb + k0 + ch * 8);
        } else {
            int r = tid >> 4, ch = tid & 15;   // 32 rows x 256B
            cp16(sb + 8192 + swzB(r, ch), B1 + (size_t)(k0 + r) * ldb + n0 + ch * 8);
        }
    };

    load_chunk(0);            CP_COMMIT();
    if (nk > 1) load_chunk(1);
    CP_COMMIT();

    for (int kc = 0; kc < nk; kc++) {
        if (kc + 2 < nk) load_chunk(kc + 2);
        CP_COMMIT();
        cp_wait<2>();
        __syncthreads();

        const uint32_t cb = sbase + (uint32_t)(kc % NSTAGE) * STAGE;
#pragma unroll
        for (int kk = 0; kk < 2; kk++) {
            const int ch = kk * 2 + lkh;
            uint32_t aH[8];
#pragma unroll
            for (int s = 0; s < 2; s++) {
                uint32_t off = swzA((uint32_t)(wm * 32 + s * 16 + lrow), ch);
                ldsm4(aH + s * 4, cb + off);
            }
#pragma unroll
            for (int q = 0; q < 2; q++) {
                uint32_t bh[4];
                if (BT) {
                    uint32_t off = swzA((uint32_t)(wn * 32 + q * 16 + lrow), ch);
                    ldsm4(bh, cb + 8192 + off);
                } else {
                    uint32_t off = swzB((uint32_t)(kk * 16 + brow),
                                        (uint32_t)(wn * 4 + q * 2 + bchh));
                    ldsm4t(bh, cb + 8192 + off);
                }
#pragma unroll
                for (int mi = 0; mi < 2; mi++) {
#pragma unroll
                    for (int sub = 0; sub < 2; sub++) {
                        float* c = acc + (mi * 4 + q * 2 + sub) * 4;
                        mma_f16(c, aH + mi * 4, bh[sub], bh[sub + 2]);
                    }
                }
            }
        }
        __syncthreads();
    }

    // ---- epilogue
    float rsum[4];   // [mi][half] row partial sums (EPI 0)
#pragma unroll
    for (int i = 0; i < 4; i++) rsum[i] = 0.f;

#pragma unroll
    for (int mi = 0; mi < 2; mi++) {
#pragma unroll
        for (int nbi = 0; nbi < 4; nbi++) {
            const float* c = acc + (mi * 4 + nbi) * 4;
            int rl = wm * 32 + mi * 16 + g;
            int cl = wn * 32 + nbi * 8 + 2 * t4;
            if (EPI == 0) {
                int gr0 = m0 + rl, gc = n0 + cl;
                float e0 = (gc     > gr0)     ? 0.f : __expf(c[0] * scale);
                float e1 = (gc + 1 > gr0)     ? 0.f : __expf(c[1] * scale);
                float e2 = (gc     > gr0 + 8) ? 0.f : __expf(c[2] * scale);
                float e3 = (gc + 1 > gr0 + 8) ? 0.f : __expf(c[3] * scale);
                *reinterpret_cast<__half2*>(Ch + (size_t)gr0 * ldc + gc) =
                    __half2(__float2half(e0), __float2half(e1));
                *reinterpret_cast<__half2*>(Ch + (size_t)(gr0 + 8) * ldc + gc) =
                    __half2(__float2half(e2), __float2half(e3));
                rsum[mi * 2 + 0] += e0 + e1;
                rsum[mi * 2 + 1] += e2 + e3;
            } else if (EPI == 1) {
                int gr0 = m0 + rl, gc = n0 + cl;
                *reinterpret_cast<float2*>(Cf + (size_t)gr0 * ldc + gc)       = make_float2(c[0], c[1]);
                *reinterpret_cast<float2*>(Cf + (size_t)(gr0 + 8) * ldc + gc) = make_float2(c[2], c[3]);
            } else {
                float s0 = 1.f, s1 = 1.f;
                if (EPI == 5) {
                    s0 = __ldg(rs + m0 + rl);
                    s1 = __ldg(rs + m0 + rl + 8);
                }
                size_t gm = (size_t)(m0 + rl);
                size_t o0 = gm * orow + cl, o1 = o0 + (size_t)8 * orow;
                *reinterpret_cast<__half2*>(O1 + o0) =
                    __half2(__float2half(c[0] * s0), __float2half(c[1] * s0));
                *reinterpret_cast<__half2*>(O1 + o1) =
                    __half2(__float2half(c[2] * s1), __float2half(c[3] * s1));
            }
        }
    }

    if (EPI == 0) {
        // reduce across t4 lanes (same row, 4 col-pairs each)
#pragma unroll
        for (int i = 0; i < 4; i++) {
            rsum[i] += __shfl_xor_sync(0xffffffffu, rsum[i], 1);
            rsum[i] += __shfl_xor_sync(0xffffffffu, rsum[i], 2);
        }
        if (t4 == 0) {
            int tn = n0 >> 7;
            float* dst = rs + ((size_t)(tn * 4 + wn)) * SS;
#pragma unroll
            for (int mi = 0; mi < 2; mi++) {
                int rl = wm * 32 + mi * 16 + g;
                dst[m0 + rl]     = rsum[mi * 2 + 0];
                dst[m0 + rl + 8] = rsum[mi * 2 + 1];
            }
        }
    }
}

// ---------------------------------------------------------------------------
__global__ void k_dummy(void) {}   // keeps scores in the ncu capture slot

__global__ void __launch_bounds__(256) k_split_all(
    const float* __restrict__ x,  const float* __restrict__ Wq,
    const float* __restrict__ Wk, const float* __restrict__ Wv,
    const float* __restrict__ Wu)
{
    const int z = blockIdx.y;
    const float* s;
    __half* h;
    switch (z) {
        case 0: s = x;  h = g_x1;  break;
        case 1: s = Wq; h = g_wq1; break;
        case 2: s = Wk; h = g_wk1; break;
        case 3: s = Wv; h = g_wv1; break;
        default: s = Wu; h = g_wu1; break;
    }
    int i = blockIdx.x * blockDim.x + threadIdx.x;
    float4 v = reinterpret_cast<const float4*>(s)[i];
    __half h0=__float2half(v.x), h1=__float2half(v.y),
           h2=__float2half(v.z), h3=__float2half(v.w);
    reinterpret_cast<uint2*>(h)[i] = make_uint2(
        (uint32_t)__half_as_ushort(h0)|((uint32_t)__half_as_ushort(h1)<<16),
        (uint32_t)__half_as_ushort(h2)|((uint32_t)__half_as_ushort(h3)<<16));
}

// QKV: 1-term x1 . W1, hi-only outputs for q, k, v.
__global__ void __launch_bounds__(512, 2) k_qkv_mma(void)
{
    int n0 = blockIdx.x * 128, m0 = blockIdx.y * 128, z = blockIdx.z;
    int b = m0 >> 11, h = n0 >> 9, e0 = n0 & 511;
    size_t base = ((size_t)(b * HH + h) * SS) * DK + e0 - (size_t)(b * SS) * DK;
    const __half* W = (z == 0) ? g_wq1 : (z == 1) ? g_wk1 : g_wv1;
    __half* O      = (z == 0) ? g_q1  : (z == 1) ? g_k1  : g_v1;
    gemm_mma<4, true>(g_x1, 512, W, 512, 512, m0, n0, 1.f,
                      nullptr, nullptr, 0, O + base, 512, nullptr);
}

// Scores+exp fused: P~ = exp(q.k * K^-0.5) with causal mask; partial row sums.
__global__ void __launch_bounds__(512, 2) k_scores_mma(void)
{
    int t = blockIdx.x, bh = blockIdx.z;
    int r = (int)((sqrtf(8.f * t + 1.f) - 1.f) * 0.5f);
    while ((r + 1) * (r + 2) / 2 <= t) r++;
    while (r * (r + 1) / 2 > t) r--;
    int c = t - r * (r + 1) / 2;
    int m0 = r * 128, n0 = c * 128;
    __half* Ch = g_p1 + (size_t)bh * SS * SS;
    float*  rs = g_rs + (size_t)bh * 16 * 4 * SS;
    size_t ob = (size_t)bh * SS * DK;
    gemm_mma<0, true>(g_q1 + ob, 512, g_k1 + ob, 512,
                      512, m0, n0, 0.04419417382415922f,
                      nullptr, Ch, SS, nullptr, 0, rs);
}

// Row-sum reduce: 1/sum over valid (tn, wn) partials. Deterministic.
__global__ void __launch_bounds__(256) k_rowsum(void)
{
    int idx = blockIdx.x * 256 + threadIdx.x;    // 0 .. NH*SS-1
    int bh = idx >> 11, r = idx & (SS - 1);
    int rt = r >> 7;
    const float* rs = g_rs + (size_t)bh * 16 * 4 * SS + r;
    float s = 0.f;
    for (int tn = 0; tn <= rt; tn++)
#pragma unroll
        for (int w = 0; w < 4; w++)
            s += rs[(size_t)(tn * 4 + w) * SS];
    g_rinv[idx] = 1.f / s;
}

// PV: 1-term P~ x v1 (NN), epilogue scales by rinv. Heavy-first m tiles.
__global__ void __launch_bounds__(512, 2) k_pv_mma(void)
{
    int bh = blockIdx.z, b = bh >> 3, h = bh & 7;
    int m0 = (15 - blockIdx.y) * 128;
    int n0 = blockIdx.x * 128;
    const __half* A1 = g_p1 + (size_t)bh * SS * SS;
    const __half* B1 = g_v1 + (size_t)bh * SS * DK;
    size_t base = (size_t)b * SS * 4096 + h * 512 + n0;
    gemm_mma<5, false>(A1, SS, B1, 512, m0 + 128, m0, n0, 1.f,
                       nullptr, nullptr, 0, g_ho1 + base, 4096,
                       g_rinv + bh * SS);
}

// out GEMM: 1-term ho1 x Wu1, k-split into 4 slices, fp32 partials.
__global__ void __launch_bounds__(512, 2) k_out_mma(void)
{
    int m0 = blockIdx.y * 128, n0 = blockIdx.x * 128, sl = blockIdx.z;
    int koff = sl * 1024;
    gemm_mma<1, true>(g_ho1 + koff, 4096, g_wu1 + koff, 4096,
                      1024, m0, n0, 1.f, g_op[sl], nullptr, 512,
                      nullptr, 0, nullptr);
}

__global__ void __launch_bounds__(256) k_reduce_out(float* __restrict__ out)
{
    int i = blockIdx.x * blockDim.x + threadIdx.x;
    float4 a = reinterpret_cast<const float4*>(g_op[0])[i];
    float4 b = reinterpret_cast<const float4*>(g_op[1])[i];
    float4 c = reinterpret_cast<const float4*>(g_op[2])[i];
    float4 d = reinterpret_cast<const float4*>(g_op[3])[i];
    float4 o;
    o.x = (a.x + b.x) + (c.x + d.x);
    o.y = (a.y + b.y) + (c.y + d.y);
    o.z = (a.z + b.z) + (c.z + d.z);
    o.w = (a.w + b.w) + (c.w + d.w);
    reinterpret_cast<float4*>(out)[i] = o;
}

// ---------------------------------------------------------------------------
extern "C" void kernel_launch(void* const* d_in, const int* in_sizes, int n_in,
                              void* d_out, int out_size)
{
    const float* x  = (const float*)d_in[0];
    const float* Wq = (const float*)d_in[1];
    const float* Wk = (const float*)d_in[2];
    const float* Wv = (const float*)d_in[3];
    const float* Wu = (const float*)d_in[4];
    float* out = (float*)d_out;

    cudaFuncSetAttribute(k_qkv_mma,    cudaFuncAttributeMaxDynamicSharedMemorySize, SMEM_DYN);
    cudaFuncSetAttribute(k_scores_mma, cudaFuncAttributeMaxDynamicSharedMemorySize, SMEM_DYN);
    cudaFuncSetAttribute(k_pv_mma,     cudaFuncAttributeMaxDynamicSharedMemorySize, SMEM_DYN);
    cudaFuncSetAttribute(k_out_mma,    cudaFuncAttributeMaxDynamicSharedMemorySize, SMEM_DYN);

    const int n4 = TT * DK / 4;
    k_dummy     <<<1, 32>>>();                                    // 1
    k_split_all <<<dim3(n4 / 256, 5), 256>>>(x, Wq, Wk, Wv, Wu);  // 2
    k_qkv_mma   <<<dim3(32, 32, 3),  512, SMEM_DYN>>>();          // 3
    k_scores_mma<<<dim3(136, 1, NH), 512, SMEM_DYN>>>();          // 4 <- ncu slot
    k_rowsum    <<<NH * SS / 256, 256>>>();
    k_pv_mma    <<<dim3(4, 16, NH),  512, SMEM_DYN>>>();
    k_out_mma   <<<dim3(4, 32, 4),   512, SMEM_DYN>>>();
    k_reduce_out<<<(TT * 512 / 4) / 256, 256>>>(out);
}